// round 1
// baseline (speedup 1.0000x reference)
#include <cuda_runtime.h>
#include <math.h>

#define HEADS  8
#define DH     64
#define BATCH  4
#define SEQ1   2048
#define NTOT   4096
#define DMODEL 1024
#define INNER  512

// ---------------- scratch (device globals; no allocations allowed) ----------
__device__ float g_q[(size_t)BATCH * HEADS * SEQ1 * DH];   // 16 MB
__device__ float g_k[(size_t)BATCH * HEADS * NTOT * DH];   // 32 MB
__device__ float g_v[(size_t)BATCH * HEADS * NTOT * DH];   // 32 MB
__device__ float g_o[(size_t)BATCH * SEQ1 * INNER];        // 16 MB

// ---------------- generic fp32 GEMM: C = A[M,K] @ W[K,N] (+bias) -----------
// HEAD_LAYOUT: scatter into [B, HEADS, Ntot, DH] at row offset roff
// (implements both the head split and the K/V concat for free).
template <bool HEAD_LAYOUT, bool BIAS>
__global__ __launch_bounds__(256)
void gemm_kernel(const float* __restrict__ A, const float* __restrict__ W,
                 const float* __restrict__ bias, float* __restrict__ C,
                 int N, int K, int Ntot, int roff)
{
    __shared__ float As[16][64];
    __shared__ float Bs[16][64];

    const int tid = threadIdx.x;
    const int tx  = tid & 15;       // 0..15 -> 4 output cols
    const int ty  = tid >> 4;       // 0..15 -> 4 output rows
    const int m0  = blockIdx.y * 64;
    const int n0  = blockIdx.x * 64;

    // A-tile loader: row lr (0..63), 4 k-values at lc
    const int lr = tid >> 2;
    const int lc = (tid & 3) * 4;
    // W-tile loader: k-row bk (0..15), 4 n-values at bn
    const int bk = tid >> 4;
    const int bn = (tid & 15) * 4;

    const float* Aptr = A + (size_t)(m0 + lr) * K + lc;
    const float* Wptr = W + (size_t)bk * N + n0 + bn;

    float acc[4][4] = {};

    for (int k0 = 0; k0 < K; k0 += 16) {
        float4 a4 = *(const float4*)(Aptr + k0);
        As[lc + 0][lr] = a4.x;
        As[lc + 1][lr] = a4.y;
        As[lc + 2][lr] = a4.z;
        As[lc + 3][lr] = a4.w;
        *(float4*)&Bs[bk][bn] = *(const float4*)(Wptr + (size_t)k0 * N);
        __syncthreads();

        #pragma unroll
        for (int kk = 0; kk < 16; kk++) {
            float4 av = *(const float4*)&As[kk][ty * 4];
            float4 bv = *(const float4*)&Bs[kk][tx * 4];
            float ar[4] = {av.x, av.y, av.z, av.w};
            float br[4] = {bv.x, bv.y, bv.z, bv.w};
            #pragma unroll
            for (int i = 0; i < 4; i++)
                #pragma unroll
                for (int j = 0; j < 4; j++)
                    acc[i][j] += ar[i] * br[j];
        }
        __syncthreads();
    }

    float4 bb = make_float4(0.f, 0.f, 0.f, 0.f);
    if (BIAS) bb = *(const float4*)&bias[n0 + tx * 4];

    #pragma unroll
    for (int i = 0; i < 4; i++) {
        int m = m0 + ty * 4 + i;
        float4 r = make_float4(acc[i][0] + bb.x, acc[i][1] + bb.y,
                               acc[i][2] + bb.z, acc[i][3] + bb.w);
        if (HEAD_LAYOUT) {
            int b  = m >> 11;           // m / SEQ1
            int ii = m & (SEQ1 - 1);
            int h  = n0 >> 6;           // tx*4 stays within one head (64)
            size_t idx = ((((size_t)b * HEADS + h) * Ntot) + roff + ii) * DH + tx * 4;
            *(float4*)&C[idx] = r;
        } else {
            *(float4*)&C[(size_t)m * N + n0 + tx * 4] = r;
        }
    }
}

// ---------------- flash attention (fp32), 1 thread = 1 query row ------------
#define BM 128   // query rows per block (= threads)
#define BN 32    // kv rows per tile

__global__ __launch_bounds__(BM)
void attn_kernel()
{
    __shared__ float4 Ks[BN * 16];   // 32 x 64 floats
    __shared__ float4 Vs[BN * 16];

    const int tid  = threadIdx.x;
    const int qrow = blockIdx.x * BM + tid;
    const int h    = blockIdx.y;
    const int b    = blockIdx.z;

    const float scale = 0.125f;  // 64^-0.5

    const float4* qptr = (const float4*)&g_q[((((size_t)b * HEADS + h) * SEQ1) + qrow) * DH];
    float4 q[16];
    #pragma unroll
    for (int i = 0; i < 16; i++) {
        q[i] = qptr[i];
        q[i].x *= scale; q[i].y *= scale; q[i].z *= scale; q[i].w *= scale;
    }

    float4 o[16];
    #pragma unroll
    for (int i = 0; i < 16; i++) o[i] = make_float4(0.f, 0.f, 0.f, 0.f);

    float mprev = -INFINITY;
    float l = 0.f;

    const float4* kbase = (const float4*)&g_k[(((size_t)b * HEADS + h) * NTOT) * DH];
    const float4* vbase = (const float4*)&g_v[(((size_t)b * HEADS + h) * NTOT) * DH];

    for (int t = 0; t < NTOT / BN; t++) {
        __syncthreads();
        #pragma unroll
        for (int i = 0; i < 4; i++) {
            Ks[tid + i * BM] = kbase[t * (BN * 16) + tid + i * BM];
            Vs[tid + i * BM] = vbase[t * (BN * 16) + tid + i * BM];
        }
        __syncthreads();

        float s[BN];
        float mt = mprev;
        #pragma unroll
        for (int j = 0; j < BN; j++) {
            float4 a = make_float4(0.f, 0.f, 0.f, 0.f);
            #pragma unroll
            for (int dq = 0; dq < 16; dq++) {
                float4 k4 = Ks[j * 16 + dq];
                a.x += q[dq].x * k4.x;
                a.y += q[dq].y * k4.y;
                a.z += q[dq].z * k4.z;
                a.w += q[dq].w * k4.w;
            }
            s[j] = (a.x + a.y) + (a.z + a.w);
            mt = fmaxf(mt, s[j]);
        }

        float c = __expf(mprev - mt);
        mprev = mt;
        l *= c;
        #pragma unroll
        for (int i = 0; i < 16; i++) {
            o[i].x *= c; o[i].y *= c; o[i].z *= c; o[i].w *= c;
        }

        #pragma unroll
        for (int j = 0; j < BN; j++) {
            float p = __expf(s[j] - mt);
            l += p;
            #pragma unroll
            for (int dq = 0; dq < 16; dq++) {
                float4 v4 = Vs[j * 16 + dq];
                o[dq].x += p * v4.x;
                o[dq].y += p * v4.y;
                o[dq].z += p * v4.z;
                o[dq].w += p * v4.w;
            }
        }
    }

    float inv = 1.f / l;
    float4* optr = (float4*)&g_o[((size_t)(b * SEQ1 + qrow)) * INNER + h * DH];
    #pragma unroll
    for (int i = 0; i < 16; i++) {
        float4 r = o[i];
        r.x *= inv; r.y *= inv; r.z *= inv; r.w *= inv;
        optr[i] = r;
    }
}

// ---------------- launch ----------------------------------------------------
extern "C" void kernel_launch(void* const* d_in, const int* in_sizes, int n_in,
                              void* d_out, int out_size)
{
    (void)in_sizes; (void)n_in; (void)out_size;
    const float* x1  = (const float*)d_in[0];
    const float* x2  = (const float*)d_in[1];
    const float* Wq1 = (const float*)d_in[2];
    const float* Wk1 = (const float*)d_in[3];
    const float* Wv1 = (const float*)d_in[4];
    const float* Wk2 = (const float*)d_in[5];
    const float* Wv2 = (const float*)d_in[6];
    const float* Wo  = (const float*)d_in[7];
    const float* bo  = (const float*)d_in[8];
    float* out = (float*)d_out;

    float *q, *k, *v, *o;
    cudaGetSymbolAddress((void**)&q, g_q);
    cudaGetSymbolAddress((void**)&k, g_k);
    cudaGetSymbolAddress((void**)&v, g_v);
    cudaGetSymbolAddress((void**)&o, g_o);

    const int M = BATCH * SEQ1;   // 8192 rows for both x1 and x2 batches
    dim3 blk(256);
    dim3 gproj(INNER / 64, M / 64);    // 8 x 128

    gemm_kernel<true, false><<<gproj, blk>>>(x1, Wq1, nullptr, q, INNER, DMODEL, SEQ1, 0);
    gemm_kernel<true, false><<<gproj, blk>>>(x1, Wk1, nullptr, k, INNER, DMODEL, NTOT, 0);
    gemm_kernel<true, false><<<gproj, blk>>>(x1, Wv1, nullptr, v, INNER, DMODEL, NTOT, 0);
    gemm_kernel<true, false><<<gproj, blk>>>(x2, Wk2, nullptr, k, INNER, DMODEL, NTOT, SEQ1);
    gemm_kernel<true, false><<<gproj, blk>>>(x2, Wv2, nullptr, v, INNER, DMODEL, NTOT, SEQ1);

    attn_kernel<<<dim3(SEQ1 / BM, HEADS, BATCH), BM>>>();

    dim3 gout(DMODEL / 64, M / 64);    // 16 x 128
    gemm_kernel<false, true><<<gout, blk>>>(o, Wo, bo, out, DMODEL, INNER, 0, 0);
}

// round 3
// speedup vs baseline: 1.3485x; 1.3485x over previous
#include <cuda_runtime.h>
#include <math.h>

#define HEADS  8
#define DH     64
#define BATCH  4
#define SEQ1   2048
#define NTOT   4096
#define DMODEL 1024
#define INNER  512

// ---------------- scratch (device globals; no allocations allowed) ----------
__device__ float g_q[(size_t)BATCH * HEADS * SEQ1 * DH];   // 16 MB
__device__ float g_k[(size_t)BATCH * HEADS * NTOT * DH];   // 32 MB
__device__ float g_v[(size_t)BATCH * HEADS * NTOT * DH];   // 32 MB
__device__ float g_o[(size_t)BATCH * SEQ1 * INNER];        // 16 MB

// ---------------- tf32 helpers ----------------------------------------------
__device__ __forceinline__ unsigned f2tf32(float f) {
    unsigned u;
    asm("cvt.rna.tf32.f32 %0, %1;" : "=r"(u) : "f"(f));
    return u;
}

__device__ __forceinline__ void mma_tf32(float* c, const unsigned* a, const unsigned* b) {
    asm volatile(
        "mma.sync.aligned.m16n8k8.row.col.f32.tf32.tf32.f32 "
        "{%0,%1,%2,%3}, {%4,%5,%6,%7}, {%8,%9}, {%0,%1,%2,%3};"
        : "+f"(c[0]), "+f"(c[1]), "+f"(c[2]), "+f"(c[3])
        : "r"(a[0]), "r"(a[1]), "r"(a[2]), "r"(a[3]), "r"(b[0]), "r"(b[1]));
}

// ---------------- tf32 tensor-core GEMM: C = A[M,K] @ W[K,N] (+bias) --------
// Block tile 128x128x32, 256 threads = 8 warps (2 m-warps x 4 n-warps),
// warp tile 64x32 (4 m-tiles x 4 n-tiles of m16n8k8).
// HEAD_LAYOUT: scatter into [B, HEADS, Ntot, DH] at row offset roff.
#define GBM 128
#define GBN 128
#define GBK 32
#define SA  36    // As row stride (floats): conflict-free fragment LDS
#define SB  136   // Bs row stride (floats): conflict-free fragment LDS

template <bool HEAD_LAYOUT, bool BIAS>
__global__ __launch_bounds__(256)
void gemm_tc_kernel(const float* __restrict__ A, const float* __restrict__ W,
                    const float* __restrict__ bias, float* __restrict__ C,
                    int N, int K, int Ntot, int roff)
{
    __shared__ unsigned As[GBM * SA];   // [m][k]
    __shared__ unsigned Bs[GBK * SB];   // [k][n]

    const int tid  = threadIdx.x;
    const int wid  = tid >> 5;
    const int lane = tid & 31;
    const int g    = lane >> 2;   // group id  (0..7)
    const int t4   = lane & 3;    // thread-in-group (0..3)

    const int m0 = blockIdx.y * GBM;
    const int n0 = blockIdx.x * GBN;
    const int wm = (wid >> 2) * 64;   // warp m offset in block (0 or 64)
    const int wn = (wid & 3) * 32;    // warp n offset in block (0..96)

    float acc[4][4][4];
    #pragma unroll
    for (int i = 0; i < 4; i++)
        #pragma unroll
        for (int j = 0; j < 4; j++)
            #pragma unroll
            for (int r = 0; r < 4; r++) acc[i][j][r] = 0.f;

    // global load indexing (float4 granularity):
    // A tile 128x32 = 1024 float4, 4/thread: f = tid + i*256 -> row=f>>3, kc=(f&7)*4
    // B tile 32x128 = 1024 float4:           f = tid + i*256 -> kr=f>>5, nc=(f&31)*4
    float4 ra[4], rb[4];

    const int T = K / GBK;

    // prologue: load tile 0
    #pragma unroll
    for (int i = 0; i < 4; i++) {
        int f = tid + i * 256;
        int row = f >> 3, kc = (f & 7) * 4;
        ra[i] = *(const float4*)(A + (size_t)(m0 + row) * K + kc);
        int kr = f >> 5, nc = (f & 31) * 4;
        rb[i] = *(const float4*)(W + (size_t)kr * N + n0 + nc);
    }

    for (int tIdx = 0; tIdx < T; tIdx++) {
        // store staged tile to smem (cvt to tf32 bit patterns)
        #pragma unroll
        for (int i = 0; i < 4; i++) {
            int f = tid + i * 256;
            int row = f >> 3, kc = (f & 7) * 4;
            unsigned* p = &As[row * SA + kc];
            p[0] = f2tf32(ra[i].x); p[1] = f2tf32(ra[i].y);
            p[2] = f2tf32(ra[i].z); p[3] = f2tf32(ra[i].w);
            int kr = f >> 5, nc = (f & 31) * 4;
            unsigned* q = &Bs[kr * SB + nc];
            q[0] = f2tf32(rb[i].x); q[1] = f2tf32(rb[i].y);
            q[2] = f2tf32(rb[i].z); q[3] = f2tf32(rb[i].w);
        }
        __syncthreads();

        // prefetch next tile into registers (overlaps with mma below)
        if (tIdx + 1 < T) {
            int k0 = (tIdx + 1) * GBK;
            #pragma unroll
            for (int i = 0; i < 4; i++) {
                int f = tid + i * 256;
                int row = f >> 3, kc = (f & 7) * 4;
                ra[i] = *(const float4*)(A + (size_t)(m0 + row) * K + k0 + kc);
                int kr = f >> 5, nc = (f & 31) * 4;
                rb[i] = *(const float4*)(W + (size_t)(k0 + kr) * N + n0 + nc);
            }
        }

        // mma over the 32-deep smem tile: 4 k-steps of 8
        const unsigned* __restrict__ Asr = As;
        const unsigned* __restrict__ Bsr = Bs;
        #pragma unroll
        for (int ks = 0; ks < 4; ks++) {
            int k = ks * 8;
            unsigned af[4][4], bf[4][2];
            #pragma unroll
            for (int mt = 0; mt < 4; mt++) {
                int r0 = wm + mt * 16 + g;
                af[mt][0] = Asr[(r0    ) * SA + k + t4];
                af[mt][1] = Asr[(r0 + 8) * SA + k + t4];
                af[mt][2] = Asr[(r0    ) * SA + k + t4 + 4];
                af[mt][3] = Asr[(r0 + 8) * SA + k + t4 + 4];
            }
            #pragma unroll
            for (int nt = 0; nt < 4; nt++) {
                int col = wn + nt * 8 + g;
                bf[nt][0] = Bsr[(k + t4    ) * SB + col];
                bf[nt][1] = Bsr[(k + t4 + 4) * SB + col];
            }
            #pragma unroll
            for (int mt = 0; mt < 4; mt++)
                #pragma unroll
                for (int nt = 0; nt < 4; nt++)
                    mma_tf32(acc[mt][nt], af[mt], bf[nt]);
        }
        __syncthreads();
    }

    // epilogue
    #pragma unroll
    for (int mt = 0; mt < 4; mt++) {
        #pragma unroll
        for (int nt = 0; nt < 4; nt++) {
            int gm0 = m0 + wm + mt * 16 + g;
            int gn  = n0 + wn + nt * 8 + 2 * t4;
            float2 v0 = make_float2(acc[mt][nt][0], acc[mt][nt][1]);
            float2 v1 = make_float2(acc[mt][nt][2], acc[mt][nt][3]);
            if (BIAS) {
                float b0 = bias[gn], b1 = bias[gn + 1];
                v0.x += b0; v0.y += b1;
                v1.x += b0; v1.y += b1;
            }
            if (HEAD_LAYOUT) {
                int h = gn >> 6;            // head (DH=64)
                int d = gn & 63;
                int b  = gm0 >> 11;         // / SEQ1
                int i0 = gm0 & (SEQ1 - 1);
                size_t base = (((size_t)b * HEADS + h) * Ntot + roff);
                *(float2*)&C[(base + i0) * DH + d]     = v0;
                *(float2*)&C[(base + i0 + 8) * DH + d] = v1;
            } else {
                *(float2*)&C[(size_t)gm0 * N + gn]       = v0;
                *(float2*)&C[(size_t)(gm0 + 8) * N + gn] = v1;
            }
        }
    }
}

// ---------------- flash attention (fp32), 1 thread = 1 query row ------------
#define BM 128   // query rows per block (= threads)
#define BN 32    // kv rows per tile

__global__ __launch_bounds__(BM)
void attn_kernel()
{
    __shared__ float4 Ks[BN * 16];   // 32 x 64 floats
    __shared__ float4 Vs[BN * 16];

    const int tid  = threadIdx.x;
    const int qrow = blockIdx.x * BM + tid;
    const int h    = blockIdx.y;
    const int b    = blockIdx.z;

    const float scale = 0.125f;  // 64^-0.5

    const float4* qptr = (const float4*)&g_q[((((size_t)b * HEADS + h) * SEQ1) + qrow) * DH];
    float4 q[16];
    #pragma unroll
    for (int i = 0; i < 16; i++) {
        q[i] = qptr[i];
        q[i].x *= scale; q[i].y *= scale; q[i].z *= scale; q[i].w *= scale;
    }

    float4 o[16];
    #pragma unroll
    for (int i = 0; i < 16; i++) o[i] = make_float4(0.f, 0.f, 0.f, 0.f);

    float mprev = -INFINITY;
    float l = 0.f;

    const float4* kbase = (const float4*)&g_k[(((size_t)b * HEADS + h) * NTOT) * DH];
    const float4* vbase = (const float4*)&g_v[(((size_t)b * HEADS + h) * NTOT) * DH];

    for (int t = 0; t < NTOT / BN; t++) {
        __syncthreads();
        #pragma unroll
        for (int i = 0; i < 4; i++) {
            Ks[tid + i * BM] = kbase[t * (BN * 16) + tid + i * BM];
            Vs[tid + i * BM] = vbase[t * (BN * 16) + tid + i * BM];
        }
        __syncthreads();

        float s[BN];
        float mt = mprev;
        #pragma unroll
        for (int j = 0; j < BN; j++) {
            float4 a = make_float4(0.f, 0.f, 0.f, 0.f);
            #pragma unroll
            for (int dq = 0; dq < 16; dq++) {
                float4 k4 = Ks[j * 16 + dq];
                a.x += q[dq].x * k4.x;
                a.y += q[dq].y * k4.y;
                a.z += q[dq].z * k4.z;
                a.w += q[dq].w * k4.w;
            }
            s[j] = (a.x + a.y) + (a.z + a.w);
            mt = fmaxf(mt, s[j]);
        }

        float c = __expf(mprev - mt);
        mprev = mt;
        l *= c;
        #pragma unroll
        for (int i = 0; i < 16; i++) {
            o[i].x *= c; o[i].y *= c; o[i].z *= c; o[i].w *= c;
        }

        #pragma unroll
        for (int j = 0; j < BN; j++) {
            float p = __expf(s[j] - mt);
            l += p;
            #pragma unroll
            for (int dq = 0; dq < 16; dq++) {
                float4 v4 = Vs[j * 16 + dq];
                o[dq].x += p * v4.x;
                o[dq].y += p * v4.y;
                o[dq].z += p * v4.z;
                o[dq].w += p * v4.w;
            }
        }
    }

    float inv = 1.f / l;
    float4* optr = (float4*)&g_o[((size_t)(b * SEQ1 + qrow)) * INNER + h * DH];
    #pragma unroll
    for (int i = 0; i < 16; i++) {
        float4 r = o[i];
        r.x *= inv; r.y *= inv; r.z *= inv; r.w *= inv;
        optr[i] = r;
    }
}

// ---------------- launch ----------------------------------------------------
extern "C" void kernel_launch(void* const* d_in, const int* in_sizes, int n_in,
                              void* d_out, int out_size)
{
    (void)in_sizes; (void)n_in; (void)out_size;
    const float* x1  = (const float*)d_in[0];
    const float* x2  = (const float*)d_in[1];
    const float* Wq1 = (const float*)d_in[2];
    const float* Wk1 = (const float*)d_in[3];
    const float* Wv1 = (const float*)d_in[4];
    const float* Wk2 = (const float*)d_in[5];
    const float* Wv2 = (const float*)d_in[6];
    const float* Wo  = (const float*)d_in[7];
    const float* bo  = (const float*)d_in[8];
    float* out = (float*)d_out;

    float *q, *k, *v, *o;
    cudaGetSymbolAddress((void**)&q, g_q);
    cudaGetSymbolAddress((void**)&k, g_k);
    cudaGetSymbolAddress((void**)&v, g_v);
    cudaGetSymbolAddress((void**)&o, g_o);

    const int M = BATCH * SEQ1;   // 8192
    dim3 blk(256);
    dim3 gproj(INNER / GBN, M / GBM);    // 4 x 64

    gemm_tc_kernel<true, false><<<gproj, blk>>>(x1, Wq1, nullptr, q, INNER, DMODEL, SEQ1, 0);
    gemm_tc_kernel<true, false><<<gproj, blk>>>(x1, Wk1, nullptr, k, INNER, DMODEL, NTOT, 0);
    gemm_tc_kernel<true, false><<<gproj, blk>>>(x1, Wv1, nullptr, v, INNER, DMODEL, NTOT, 0);
    gemm_tc_kernel<true, false><<<gproj, blk>>>(x2, Wk2, nullptr, k, INNER, DMODEL, NTOT, SEQ1);
    gemm_tc_kernel<true, false><<<gproj, blk>>>(x2, Wv2, nullptr, v, INNER, DMODEL, NTOT, SEQ1);

    attn_kernel<<<dim3(SEQ1 / BM, HEADS, BATCH), BM>>>();

    dim3 gout(DMODEL / GBN, M / GBM);    // 8 x 64
    gemm_tc_kernel<false, true><<<gout, blk>>>(o, Wo, bo, out, DMODEL, INNER, 0, 0);
}

// round 5
// speedup vs baseline: 2.9007x; 2.1510x over previous
#include <cuda_runtime.h>
#include <math.h>

#define HEADS  8
#define DH     64
#define BATCH  4
#define SEQ1   2048
#define NTOT   4096
#define DMODEL 1024
#define INNER  512

// ---------------- scratch (device globals; no allocations allowed) ----------
__device__ float g_q[(size_t)BATCH * HEADS * SEQ1 * DH];   // 16 MB
__device__ float g_k[(size_t)BATCH * HEADS * NTOT * DH];   // 32 MB
__device__ float g_v[(size_t)BATCH * HEADS * NTOT * DH];   // 32 MB
__device__ float g_o[(size_t)BATCH * SEQ1 * INNER];        // 16 MB

// ---------------- tf32 helpers ----------------------------------------------
__device__ __forceinline__ unsigned f2tf32(float f) {
    unsigned u;
    asm("cvt.rna.tf32.f32 %0, %1;" : "=r"(u) : "f"(f));
    return u;
}

__device__ __forceinline__ void mma_tf32(float* c, const unsigned* a, const unsigned* b) {
    asm volatile(
        "mma.sync.aligned.m16n8k8.row.col.f32.tf32.tf32.f32 "
        "{%0,%1,%2,%3}, {%4,%5,%6,%7}, {%8,%9}, {%0,%1,%2,%3};"
        : "+f"(c[0]), "+f"(c[1]), "+f"(c[2]), "+f"(c[3])
        : "r"(a[0]), "r"(a[1]), "r"(a[2]), "r"(a[3]), "r"(b[0]), "r"(b[1]));
}

// ---------------- tf32 tensor-core GEMM: C = A[M,K] @ W[K,N] (+bias) --------
#define GBM 128
#define GBN 128
#define GBK 32
#define SA  36
#define SB  136

template <bool HEAD_LAYOUT, bool BIAS>
__global__ __launch_bounds__(256)
void gemm_tc_kernel(const float* __restrict__ A, const float* __restrict__ W,
                    const float* __restrict__ bias, float* __restrict__ C,
                    int N, int K, int Ntot, int roff)
{
    __shared__ unsigned As[GBM * SA];   // [m][k]
    __shared__ unsigned Bs[GBK * SB];   // [k][n]

    const int tid  = threadIdx.x;
    const int wid  = tid >> 5;
    const int lane = tid & 31;
    const int g    = lane >> 2;
    const int t4   = lane & 3;

    const int m0 = blockIdx.y * GBM;
    const int n0 = blockIdx.x * GBN;
    const int wm = (wid >> 2) * 64;
    const int wn = (wid & 3) * 32;

    float acc[4][4][4];
    #pragma unroll
    for (int i = 0; i < 4; i++)
        #pragma unroll
        for (int j = 0; j < 4; j++)
            #pragma unroll
            for (int r = 0; r < 4; r++) acc[i][j][r] = 0.f;

    float4 ra[4], rb[4];
    const int T = K / GBK;

    #pragma unroll
    for (int i = 0; i < 4; i++) {
        int f = tid + i * 256;
        int row = f >> 3, kc = (f & 7) * 4;
        ra[i] = *(const float4*)(A + (size_t)(m0 + row) * K + kc);
        int kr = f >> 5, nc = (f & 31) * 4;
        rb[i] = *(const float4*)(W + (size_t)kr * N + n0 + nc);
    }

    for (int tIdx = 0; tIdx < T; tIdx++) {
        #pragma unroll
        for (int i = 0; i < 4; i++) {
            int f = tid + i * 256;
            int row = f >> 3, kc = (f & 7) * 4;
            unsigned* p = &As[row * SA + kc];
            p[0] = f2tf32(ra[i].x); p[1] = f2tf32(ra[i].y);
            p[2] = f2tf32(ra[i].z); p[3] = f2tf32(ra[i].w);
            int kr = f >> 5, nc = (f & 31) * 4;
            unsigned* q = &Bs[kr * SB + nc];
            q[0] = f2tf32(rb[i].x); q[1] = f2tf32(rb[i].y);
            q[2] = f2tf32(rb[i].z); q[3] = f2tf32(rb[i].w);
        }
        __syncthreads();

        if (tIdx + 1 < T) {
            int k0 = (tIdx + 1) * GBK;
            #pragma unroll
            for (int i = 0; i < 4; i++) {
                int f = tid + i * 256;
                int row = f >> 3, kc = (f & 7) * 4;
                ra[i] = *(const float4*)(A + (size_t)(m0 + row) * K + k0 + kc);
                int kr = f >> 5, nc = (f & 31) * 4;
                rb[i] = *(const float4*)(W + (size_t)(k0 + kr) * N + n0 + nc);
            }
        }

        const unsigned* __restrict__ Asr = As;
        const unsigned* __restrict__ Bsr = Bs;
        #pragma unroll
        for (int ks = 0; ks < 4; ks++) {
            int k = ks * 8;
            unsigned af[4][4], bf[4][2];
            #pragma unroll
            for (int mt = 0; mt < 4; mt++) {
                int r0 = wm + mt * 16 + g;
                af[mt][0] = Asr[(r0    ) * SA + k + t4];
                af[mt][1] = Asr[(r0 + 8) * SA + k + t4];
                af[mt][2] = Asr[(r0    ) * SA + k + t4 + 4];
                af[mt][3] = Asr[(r0 + 8) * SA + k + t4 + 4];
            }
            #pragma unroll
            for (int nt = 0; nt < 4; nt++) {
                int col = wn + nt * 8 + g;
                bf[nt][0] = Bsr[(k + t4    ) * SB + col];
                bf[nt][1] = Bsr[(k + t4 + 4) * SB + col];
            }
            #pragma unroll
            for (int mt = 0; mt < 4; mt++)
                #pragma unroll
                for (int nt = 0; nt < 4; nt++)
                    mma_tf32(acc[mt][nt], af[mt], bf[nt]);
        }
        __syncthreads();
    }

    #pragma unroll
    for (int mt = 0; mt < 4; mt++) {
        #pragma unroll
        for (int nt = 0; nt < 4; nt++) {
            int gm0 = m0 + wm + mt * 16 + g;
            int gn  = n0 + wn + nt * 8 + 2 * t4;
            float2 v0 = make_float2(acc[mt][nt][0], acc[mt][nt][1]);
            float2 v1 = make_float2(acc[mt][nt][2], acc[mt][nt][3]);
            if (BIAS) {
                float b0 = bias[gn], b1 = bias[gn + 1];
                v0.x += b0; v0.y += b1;
                v1.x += b0; v1.y += b1;
            }
            if (HEAD_LAYOUT) {
                int h = gn >> 6;
                int d = gn & 63;
                int b  = gm0 >> 11;
                int i0 = gm0 & (SEQ1 - 1);
                size_t base = (((size_t)b * HEADS + h) * Ntot + roff);
                *(float2*)&C[(base + i0) * DH + d]     = v0;
                *(float2*)&C[(base + i0 + 8) * DH + d] = v1;
            } else {
                *(float2*)&C[(size_t)gm0 * N + gn]       = v0;
                *(float2*)&C[(size_t)(gm0 + 8) * N + gn] = v1;
            }
        }
    }
}

// ---------------- tf32 tensor-core flash attention ---------------------------
// Br=128 q-rows per CTA (8 warps x 16 rows), Bc=64 kv per iteration.
// QK^T: Q split hi/lo (2 mmas) -> K-rounding-only error. PV: plain tf32.
#define ABR 128
#define ABC 64
#define SKS 68   // Ks row stride (floats): b-frag lanes 4g+t4 -> conflict-free
#define SVS 72   // Vs row stride: b-frag lanes 8t4+g -> conflict-free
#define SPS 68   // Ps row stride: a-frag lanes 4g+t4 -> conflict-free

#define ATTN_SMEM ((64 * SKS + 64 * SVS + 8 * 16 * SPS) * 4)   // 70656 B

__global__ __launch_bounds__(256, 1)
void attn_tc_kernel()
{
    extern __shared__ float sm[];
    unsigned* Ksu = (unsigned*)sm;                       // [64][SKS] (n=kv, k=dh)
    unsigned* Vsu = (unsigned*)(sm + 64 * SKS);          // [64][SVS] (k=kv, n=dh)
    unsigned* Psu = (unsigned*)(sm + 64 * SKS + 64 * SVS); // 8 x [16][SPS]

    const int tid  = threadIdx.x;
    const int wid  = tid >> 5;
    const int lane = tid & 31;
    const int g    = lane >> 2;
    const int t4   = lane & 3;
    const int wm   = wid * 16;

    const int qb = blockIdx.x, h = blockIdx.y, b = blockIdx.z;

    const float* Qg = g_q + (((size_t)b * HEADS + h) * SEQ1 + qb * ABR) * DH;
    const float* Kg = g_k + ((size_t)b * HEADS + h) * NTOT * DH;
    const float* Vg = g_v + ((size_t)b * HEADS + h) * NTOT * DH;

    // ---- stage Q (coalesced) into smem, stride SKS -------------------------
    #pragma unroll
    for (int i = 0; i < 8; i++) {                 // 128x16 float4 = 2048 / 256
        int f = tid + i * 256;
        int row = f >> 4, c4 = (f & 15) * 4;
        float4 v = *(const float4*)(Qg + row * DH + c4);
        float* p = sm + row * SKS + c4;
        p[0] = v.x; p[1] = v.y; p[2] = v.z; p[3] = v.w;
    }
    __syncthreads();

    // ---- extract Q a-frags (hi/lo split), scaled ---------------------------
    const float scale = 0.125f;
    unsigned qh[8][4], ql[8][4];
    #pragma unroll
    for (int ks = 0; ks < 8; ks++) {
        int col = ks * 8 + t4;
        float v0 = sm[(wm + g    ) * SKS + col    ] * scale;
        float v1 = sm[(wm + g + 8) * SKS + col    ] * scale;
        float v2 = sm[(wm + g    ) * SKS + col + 4] * scale;
        float v3 = sm[(wm + g + 8) * SKS + col + 4] * scale;
        qh[ks][0] = f2tf32(v0); ql[ks][0] = f2tf32(v0 - __uint_as_float(qh[ks][0]));
        qh[ks][1] = f2tf32(v1); ql[ks][1] = f2tf32(v1 - __uint_as_float(qh[ks][1]));
        qh[ks][2] = f2tf32(v2); ql[ks][2] = f2tf32(v2 - __uint_as_float(qh[ks][2]));
        qh[ks][3] = f2tf32(v3); ql[ks][3] = f2tf32(v3 - __uint_as_float(qh[ks][3]));
    }
    __syncthreads();

    unsigned* Pw = Psu + wid * 16 * SPS;

    float out[8][4];
    #pragma unroll
    for (int nt = 0; nt < 8; nt++)
        #pragma unroll
        for (int r = 0; r < 4; r++) out[nt][r] = 0.f;

    float m0 = -INFINITY, m1 = -INFINITY, l0 = 0.f, l1 = 0.f;

    for (int it = 0; it < NTOT / ABC; it++) {
        // ---- load K,V tile (convert to tf32 at store) ----------------------
        const float* kt = Kg + (size_t)it * ABC * DH;
        const float* vt = Vg + (size_t)it * ABC * DH;
        #pragma unroll
        for (int i = 0; i < 4; i++) {             // 64x16 float4 = 1024 / 256
            int f = tid + i * 256;
            int row = f >> 4, c4 = (f & 15) * 4;
            float4 kv = *(const float4*)(kt + row * DH + c4);
            unsigned* p = &Ksu[row * SKS + c4];
            p[0] = f2tf32(kv.x); p[1] = f2tf32(kv.y);
            p[2] = f2tf32(kv.z); p[3] = f2tf32(kv.w);
            float4 vv = *(const float4*)(vt + row * DH + c4);
            unsigned* q = &Vsu[row * SVS + c4];
            q[0] = f2tf32(vv.x); q[1] = f2tf32(vv.y);
            q[2] = f2tf32(vv.z); q[3] = f2tf32(vv.w);
        }
        __syncthreads();

        // ---- S = Q K^T (hi + lo) ------------------------------------------
        float s[8][4];
        #pragma unroll
        for (int nt = 0; nt < 8; nt++)
            #pragma unroll
            for (int r = 0; r < 4; r++) s[nt][r] = 0.f;

        #pragma unroll
        for (int ks = 0; ks < 8; ks++) {
            unsigned bf[8][2];
            #pragma unroll
            for (int nt = 0; nt < 8; nt++) {
                bf[nt][0] = Ksu[(nt * 8 + g) * SKS + ks * 8 + t4    ];
                bf[nt][1] = Ksu[(nt * 8 + g) * SKS + ks * 8 + t4 + 4];
            }
            #pragma unroll
            for (int nt = 0; nt < 8; nt++) {
                mma_tf32(s[nt], qh[ks], bf[nt]);
                mma_tf32(s[nt], ql[ks], bf[nt]);
            }
        }

        // ---- online softmax -----------------------------------------------
        float mx0 = m0, mx1 = m1;
        #pragma unroll
        for (int nt = 0; nt < 8; nt++) {
            mx0 = fmaxf(mx0, fmaxf(s[nt][0], s[nt][1]));
            mx1 = fmaxf(mx1, fmaxf(s[nt][2], s[nt][3]));
        }
        mx0 = fmaxf(mx0, __shfl_xor_sync(0xffffffffu, mx0, 1));
        mx0 = fmaxf(mx0, __shfl_xor_sync(0xffffffffu, mx0, 2));
        mx1 = fmaxf(mx1, __shfl_xor_sync(0xffffffffu, mx1, 1));
        mx1 = fmaxf(mx1, __shfl_xor_sync(0xffffffffu, mx1, 2));

        float c0 = __expf(m0 - mx0);
        float c1 = __expf(m1 - mx1);
        m0 = mx0; m1 = mx1;

        float rs0 = 0.f, rs1 = 0.f;
        #pragma unroll
        for (int nt = 0; nt < 8; nt++) {
            float p0 = __expf(s[nt][0] - m0);
            float p1 = __expf(s[nt][1] - m0);
            float p2 = __expf(s[nt][2] - m1);
            float p3 = __expf(s[nt][3] - m1);
            rs0 += p0 + p1;
            rs1 += p2 + p3;
            Pw[(g    ) * SPS + nt * 8 + 2 * t4    ] = f2tf32(p0);
            Pw[(g    ) * SPS + nt * 8 + 2 * t4 + 1] = f2tf32(p1);
            Pw[(g + 8) * SPS + nt * 8 + 2 * t4    ] = f2tf32(p2);
            Pw[(g + 8) * SPS + nt * 8 + 2 * t4 + 1] = f2tf32(p3);
        }
        rs0 += __shfl_xor_sync(0xffffffffu, rs0, 1);
        rs0 += __shfl_xor_sync(0xffffffffu, rs0, 2);
        rs1 += __shfl_xor_sync(0xffffffffu, rs1, 1);
        rs1 += __shfl_xor_sync(0xffffffffu, rs1, 2);
        l0 = l0 * c0 + rs0;
        l1 = l1 * c1 + rs1;

        #pragma unroll
        for (int nt = 0; nt < 8; nt++) {
            out[nt][0] *= c0; out[nt][1] *= c0;
            out[nt][2] *= c1; out[nt][3] *= c1;
        }
        __syncwarp();

        // ---- out += P V ----------------------------------------------------
        #pragma unroll
        for (int ks = 0; ks < 8; ks++) {
            unsigned af[4];
            af[0] = Pw[(g    ) * SPS + ks * 8 + t4    ];
            af[1] = Pw[(g + 8) * SPS + ks * 8 + t4    ];
            af[2] = Pw[(g    ) * SPS + ks * 8 + t4 + 4];
            af[3] = Pw[(g + 8) * SPS + ks * 8 + t4 + 4];
            #pragma unroll
            for (int nt = 0; nt < 8; nt++) {
                unsigned bf2[2];
                bf2[0] = Vsu[(ks * 8 + t4    ) * SVS + nt * 8 + g];
                bf2[1] = Vsu[(ks * 8 + t4 + 4) * SVS + nt * 8 + g];
                mma_tf32(out[nt], af, bf2);
            }
        }
        __syncthreads();   // protect Ks/Vs before next iteration's overwrite
    }

    // ---- epilogue: normalize, write to g_o in [B, N1, h*64+d] --------------
    float inv0 = 1.f / l0;
    float inv1 = 1.f / l1;
    int r0 = qb * ABR + wm + g;
    int r1 = r0 + 8;
    float* o0 = g_o + ((size_t)b * SEQ1 + r0) * INNER + h * DH;
    float* o1 = g_o + ((size_t)b * SEQ1 + r1) * INNER + h * DH;
    #pragma unroll
    for (int nt = 0; nt < 8; nt++) {
        int col = nt * 8 + 2 * t4;
        *(float2*)&o0[col] = make_float2(out[nt][0] * inv0, out[nt][1] * inv0);
        *(float2*)&o1[col] = make_float2(out[nt][2] * inv1, out[nt][3] * inv1);
    }
}

// ---------------- launch ----------------------------------------------------
extern "C" void kernel_launch(void* const* d_in, const int* in_sizes, int n_in,
                              void* d_out, int out_size)
{
    (void)in_sizes; (void)n_in; (void)out_size;
    const float* x1  = (const float*)d_in[0];
    const float* x2  = (const float*)d_in[1];
    const float* Wq1 = (const float*)d_in[2];
    const float* Wk1 = (const float*)d_in[3];
    const float* Wv1 = (const float*)d_in[4];
    const float* Wk2 = (const float*)d_in[5];
    const float* Wv2 = (const float*)d_in[6];
    const float* Wo  = (const float*)d_in[7];
    const float* bo  = (const float*)d_in[8];
    float* out = (float*)d_out;

    float *q, *k, *v, *o;
    cudaGetSymbolAddress((void**)&q, g_q);
    cudaGetSymbolAddress((void**)&k, g_k);
    cudaGetSymbolAddress((void**)&v, g_v);
    cudaGetSymbolAddress((void**)&o, g_o);

    cudaFuncSetAttribute(attn_tc_kernel,
                         cudaFuncAttributeMaxDynamicSharedMemorySize, ATTN_SMEM);

    const int M = BATCH * SEQ1;   // 8192
    dim3 blk(256);
    dim3 gproj(INNER / GBN, M / GBM);    // 4 x 64

    gemm_tc_kernel<true, false><<<gproj, blk>>>(x1, Wq1, nullptr, q, INNER, DMODEL, SEQ1, 0);
    gemm_tc_kernel<true, false><<<gproj, blk>>>(x1, Wk1, nullptr, k, INNER, DMODEL, NTOT, 0);
    gemm_tc_kernel<true, false><<<gproj, blk>>>(x1, Wv1, nullptr, v, INNER, DMODEL, NTOT, 0);
    gemm_tc_kernel<true, false><<<gproj, blk>>>(x2, Wk2, nullptr, k, INNER, DMODEL, NTOT, SEQ1);
    gemm_tc_kernel<true, false><<<gproj, blk>>>(x2, Wv2, nullptr, v, INNER, DMODEL, NTOT, SEQ1);

    attn_tc_kernel<<<dim3(SEQ1 / ABR, HEADS, BATCH), blk, ATTN_SMEM>>>();

    dim3 gout(DMODEL / GBN, M / GBM);    // 8 x 64
    gemm_tc_kernel<false, true><<<gout, blk>>>(o, Wo, bo, out, DMODEL, INNER, 0, 0);
}

// round 7
// speedup vs baseline: 3.3475x; 1.1540x over previous
#include <cuda_runtime.h>
#include <math.h>

#define HEADS  8
#define DH     64
#define BATCH  4
#define SEQ1   2048
#define NTOT   4096
#define DMODEL 1024
#define INNER  512

// ---------------- scratch (device globals; no allocations allowed) ----------
__device__ float g_q[(size_t)BATCH * HEADS * SEQ1 * DH];   // 16 MB
__device__ float g_k[(size_t)BATCH * HEADS * NTOT * DH];   // 32 MB
__device__ float g_v[(size_t)BATCH * HEADS * NTOT * DH];   // 32 MB
__device__ float g_o[(size_t)BATCH * SEQ1 * INNER];        // 16 MB

// ---------------- tf32 helpers ----------------------------------------------
__device__ __forceinline__ unsigned f2tf32(float f) {
    unsigned u;
    asm("cvt.rna.tf32.f32 %0, %1;" : "=r"(u) : "f"(f));
    return u;
}

__device__ __forceinline__ void mma_tf32(float* c, const unsigned* a, const unsigned* b) {
    asm volatile(
        "mma.sync.aligned.m16n8k8.row.col.f32.tf32.tf32.f32 "
        "{%0,%1,%2,%3}, {%4,%5,%6,%7}, {%8,%9}, {%0,%1,%2,%3};"
        : "+f"(c[0]), "+f"(c[1]), "+f"(c[2]), "+f"(c[3])
        : "r"(a[0]), "r"(a[1]), "r"(a[2]), "r"(a[3]), "r"(b[0]), "r"(b[1]));
}

// ---------------- tf32 GEMM core: C = A[M,K] @ W[K,N] (+bias) ---------------
// Block tile 128x128x32, 256 threads, double-buffered smem, 1 sync/iter.
#define GBM 128
#define GBN 128
#define GBK 32
#define SA  36
#define SB  136
#define ASZ (GBM * SA)        // 4608 words
#define BSZ (GBK * SB)        // 4352 words
#define GEMM_SMEM ((ASZ + BSZ) * 2 * 4)   // 71680 B

template <bool HEAD_LAYOUT, bool BIAS>
__device__ __forceinline__ void gemm_core(
    const float* __restrict__ A, const float* __restrict__ W,
    const float* __restrict__ bias, float* __restrict__ C,
    int N, int K, int Ntot, int roff, unsigned* smu)
{
    unsigned* Ac = smu;
    unsigned* An = smu + ASZ;
    unsigned* Bc = smu + 2 * ASZ;
    unsigned* Bn = smu + 2 * ASZ + BSZ;

    const int tid  = threadIdx.x;
    const int wid  = tid >> 5;
    const int lane = tid & 31;
    const int g    = lane >> 2;
    const int t4   = lane & 3;

    const int m0 = blockIdx.y * GBM;
    const int n0 = blockIdx.x * GBN;
    const int wm = (wid >> 2) * 64;
    const int wn = (wid & 3) * 32;

    float acc[4][4][4];
    #pragma unroll
    for (int i = 0; i < 4; i++)
        #pragma unroll
        for (int j = 0; j < 4; j++)
            #pragma unroll
            for (int r = 0; r < 4; r++) acc[i][j][r] = 0.f;

    float4 ra[4], rb[4];
    const int T = K / GBK;

    // prologue: LDG tile 0, STS buf0
    #pragma unroll
    for (int i = 0; i < 4; i++) {
        int f = tid + i * 256;
        int row = f >> 3, kc = (f & 7) * 4;
        ra[i] = *(const float4*)(A + (size_t)(m0 + row) * K + kc);
        int kr = f >> 5, nc = (f & 31) * 4;
        rb[i] = *(const float4*)(W + (size_t)kr * N + n0 + nc);
    }
    #pragma unroll
    for (int i = 0; i < 4; i++) {
        int f = tid + i * 256;
        int row = f >> 3, kc = (f & 7) * 4;
        unsigned* p = &Ac[row * SA + kc];
        p[0] = f2tf32(ra[i].x); p[1] = f2tf32(ra[i].y);
        p[2] = f2tf32(ra[i].z); p[3] = f2tf32(ra[i].w);
        int kr = f >> 5, nc = (f & 31) * 4;
        unsigned* q = &Bc[kr * SB + nc];
        q[0] = f2tf32(rb[i].x); q[1] = f2tf32(rb[i].y);
        q[2] = f2tf32(rb[i].z); q[3] = f2tf32(rb[i].w);
    }
    __syncthreads();

    for (int tIdx = 0; tIdx < T; tIdx++) {
        const bool more = (tIdx + 1 < T);
        if (more) {
            int k0 = (tIdx + 1) * GBK;
            #pragma unroll
            for (int i = 0; i < 4; i++) {
                int f = tid + i * 256;
                int row = f >> 3, kc = (f & 7) * 4;
                ra[i] = *(const float4*)(A + (size_t)(m0 + row) * K + k0 + kc);
                int kr = f >> 5, nc = (f & 31) * 4;
                rb[i] = *(const float4*)(W + (size_t)(k0 + kr) * N + n0 + nc);
            }
        }

        // MMA on current buffers
        #pragma unroll
        for (int ks = 0; ks < 4; ks++) {
            int k = ks * 8;
            unsigned af[4][4], bf[4][2];
            #pragma unroll
            for (int mt = 0; mt < 4; mt++) {
                int r0 = wm + mt * 16 + g;
                af[mt][0] = Ac[(r0    ) * SA + k + t4];
                af[mt][1] = Ac[(r0 + 8) * SA + k + t4];
                af[mt][2] = Ac[(r0    ) * SA + k + t4 + 4];
                af[mt][3] = Ac[(r0 + 8) * SA + k + t4 + 4];
            }
            #pragma unroll
            for (int nt = 0; nt < 4; nt++) {
                int col = wn + nt * 8 + g;
                bf[nt][0] = Bc[(k + t4    ) * SB + col];
                bf[nt][1] = Bc[(k + t4 + 4) * SB + col];
            }
            #pragma unroll
            for (int mt = 0; mt < 4; mt++)
                #pragma unroll
                for (int nt = 0; nt < 4; nt++)
                    mma_tf32(acc[mt][nt], af[mt], bf[nt]);
        }

        if (more) {
            #pragma unroll
            for (int i = 0; i < 4; i++) {
                int f = tid + i * 256;
                int row = f >> 3, kc = (f & 7) * 4;
                unsigned* p = &An[row * SA + kc];
                p[0] = f2tf32(ra[i].x); p[1] = f2tf32(ra[i].y);
                p[2] = f2tf32(ra[i].z); p[3] = f2tf32(ra[i].w);
                int kr = f >> 5, nc = (f & 31) * 4;
                unsigned* q = &Bn[kr * SB + nc];
                q[0] = f2tf32(rb[i].x); q[1] = f2tf32(rb[i].y);
                q[2] = f2tf32(rb[i].z); q[3] = f2tf32(rb[i].w);
            }
        }
        __syncthreads();
        unsigned* t;
        t = Ac; Ac = An; An = t;
        t = Bc; Bc = Bn; Bn = t;
    }

    // epilogue
    #pragma unroll
    for (int mt = 0; mt < 4; mt++) {
        #pragma unroll
        for (int nt = 0; nt < 4; nt++) {
            int gm0 = m0 + wm + mt * 16 + g;
            int gn  = n0 + wn + nt * 8 + 2 * t4;
            float2 v0 = make_float2(acc[mt][nt][0], acc[mt][nt][1]);
            float2 v1 = make_float2(acc[mt][nt][2], acc[mt][nt][3]);
            if (BIAS) {
                float b0 = bias[gn], b1 = bias[gn + 1];
                v0.x += b0; v0.y += b1;
                v1.x += b0; v1.y += b1;
            }
            if (HEAD_LAYOUT) {
                int h = gn >> 6;
                int d = gn & 63;
                int b  = gm0 >> 11;
                int i0 = gm0 & (SEQ1 - 1);
                size_t base = (((size_t)b * HEADS + h) * Ntot + roff);
                *(float2*)&C[(base + i0) * DH + d]     = v0;
                *(float2*)&C[(base + i0 + 8) * DH + d] = v1;
            } else {
                *(float2*)&C[(size_t)gm0 * N + gn]       = v0;
                *(float2*)&C[(size_t)(gm0 + 8) * N + gn] = v1;
            }
        }
    }
}

// merged projection launch: grid.z selects which of the 5 GEMMs
__global__ __launch_bounds__(256, 1)
void proj_kernel(const float* __restrict__ x1, const float* __restrict__ x2,
                 const float* __restrict__ Wq1, const float* __restrict__ Wk1,
                 const float* __restrict__ Wv1, const float* __restrict__ Wk2,
                 const float* __restrict__ Wv2,
                 float* __restrict__ q, float* __restrict__ k, float* __restrict__ v)
{
    extern __shared__ unsigned smu[];
    const float* A; const float* W; float* C; int Ntot; int roff;
    switch (blockIdx.z) {
        case 0:  A = x1; W = Wq1; C = q; Ntot = SEQ1; roff = 0;    break;
        case 1:  A = x1; W = Wk1; C = k; Ntot = NTOT; roff = 0;    break;
        case 2:  A = x1; W = Wv1; C = v; Ntot = NTOT; roff = 0;    break;
        case 3:  A = x2; W = Wk2; C = k; Ntot = NTOT; roff = SEQ1; break;
        default: A = x2; W = Wv2; C = v; Ntot = NTOT; roff = SEQ1; break;
    }
    gemm_core<true, false>(A, W, nullptr, C, INNER, DMODEL, Ntot, roff, smu);
}

__global__ __launch_bounds__(256, 1)
void out_kernel(const float* __restrict__ A, const float* __restrict__ W,
                const float* __restrict__ bias, float* __restrict__ C)
{
    extern __shared__ unsigned smu[];
    gemm_core<false, true>(A, W, bias, C, DMODEL, INNER, 0, 0, smu);
}

// ---------------- tf32 tensor-core flash attention ---------------------------
// Br=128 q-rows per CTA (8 warps x 16 rows), Bc=64 kv per iteration.
// Double-buffered K/V smem, register prefetch, 1 syncthreads per iteration.
#define ABR 128
#define ABC 64
#define SKS 68
#define SVS 72
#define SPS 68
#define KSZ (64 * SKS)   // 4352 words
#define VSZ (64 * SVS)   // 4608 words
#define ATTN_SMEM ((2 * KSZ + 2 * VSZ + 8 * 16 * SPS) * 4)   // 106496 B

__global__ __launch_bounds__(256, 1)
void attn_tc_kernel()
{
    extern __shared__ float sm[];
    unsigned* Kc = (unsigned*)sm;
    unsigned* Kn = (unsigned*)sm + KSZ;
    unsigned* Vc = (unsigned*)sm + 2 * KSZ;
    unsigned* Vn = (unsigned*)sm + 2 * KSZ + VSZ;
    unsigned* Psu = (unsigned*)sm + 2 * KSZ + 2 * VSZ;

    const int tid  = threadIdx.x;
    const int wid  = tid >> 5;
    const int lane = tid & 31;
    const int g    = lane >> 2;
    const int t4   = lane & 3;
    const int wm   = wid * 16;

    const int qb = blockIdx.x, h = blockIdx.y, b = blockIdx.z;

    const float* Qg = g_q + (((size_t)b * HEADS + h) * SEQ1 + qb * ABR) * DH;
    const float* Kg = g_k + ((size_t)b * HEADS + h) * NTOT * DH;
    const float* Vg = g_v + ((size_t)b * HEADS + h) * NTOT * DH;

    // ---- stage Q into sm[0 .. 128*SKS) (aliases K buffers; freed before use)
    #pragma unroll
    for (int i = 0; i < 8; i++) {
        int f = tid + i * 256;
        int row = f >> 4, c4 = (f & 15) * 4;
        float4 v = *(const float4*)(Qg + row * DH + c4);
        float* p = sm + row * SKS + c4;
        p[0] = v.x; p[1] = v.y; p[2] = v.z; p[3] = v.w;
    }
    __syncthreads();

    // ---- extract Q a-frags (hi/lo split), scaled ---------------------------
    const float scale = 0.125f;
    unsigned qh[8][4], ql[8][4];
    #pragma unroll
    for (int ks = 0; ks < 8; ks++) {
        int col = ks * 8 + t4;
        float v0 = sm[(wm + g    ) * SKS + col    ] * scale;
        float v1 = sm[(wm + g + 8) * SKS + col    ] * scale;
        float v2 = sm[(wm + g    ) * SKS + col + 4] * scale;
        float v3 = sm[(wm + g + 8) * SKS + col + 4] * scale;
        qh[ks][0] = f2tf32(v0); ql[ks][0] = f2tf32(v0 - __uint_as_float(qh[ks][0]));
        qh[ks][1] = f2tf32(v1); ql[ks][1] = f2tf32(v1 - __uint_as_float(qh[ks][1]));
        qh[ks][2] = f2tf32(v2); ql[ks][2] = f2tf32(v2 - __uint_as_float(qh[ks][2]));
        qh[ks][3] = f2tf32(v3); ql[ks][3] = f2tf32(v3 - __uint_as_float(qh[ks][3]));
    }
    __syncthreads();

    unsigned* Pw = Psu + wid * 16 * SPS;

    float out[8][4];
    #pragma unroll
    for (int nt = 0; nt < 8; nt++)
        #pragma unroll
        for (int r = 0; r < 4; r++) out[nt][r] = 0.f;

    float m0 = -INFINITY, m1 = -INFINITY, l0 = 0.f, l1 = 0.f;

    float4 rk[4], rv[4];
    const int T = NTOT / ABC;

    // ---- prologue: LDG tile 0 + STS into current buffers -------------------
    #pragma unroll
    for (int i = 0; i < 4; i++) {
        int f = tid + i * 256;
        int row = f >> 4, c4 = (f & 15) * 4;
        rk[i] = *(const float4*)(Kg + row * DH + c4);
        rv[i] = *(const float4*)(Vg + row * DH + c4);
    }
    #pragma unroll
    for (int i = 0; i < 4; i++) {
        int f = tid + i * 256;
        int row = f >> 4, c4 = (f & 15) * 4;
        unsigned* p = &Kc[row * SKS + c4];
        p[0] = f2tf32(rk[i].x); p[1] = f2tf32(rk[i].y);
        p[2] = f2tf32(rk[i].z); p[3] = f2tf32(rk[i].w);
        unsigned* q = &Vc[row * SVS + c4];
        q[0] = f2tf32(rv[i].x); q[1] = f2tf32(rv[i].y);
        q[2] = f2tf32(rv[i].z); q[3] = f2tf32(rv[i].w);
    }
    __syncthreads();

    for (int it = 0; it < T; it++) {
        const bool more = (it + 1 < T);
        if (more) {
            const float* kt = Kg + (size_t)(it + 1) * ABC * DH;
            const float* vt = Vg + (size_t)(it + 1) * ABC * DH;
            #pragma unroll
            for (int i = 0; i < 4; i++) {
                int f = tid + i * 256;
                int row = f >> 4, c4 = (f & 15) * 4;
                rk[i] = *(const float4*)(kt + row * DH + c4);
                rv[i] = *(const float4*)(vt + row * DH + c4);
            }
        }

        // ---- S = Q K^T (hi + lo) ------------------------------------------
        float s[8][4];
        #pragma unroll
        for (int nt = 0; nt < 8; nt++)
            #pragma unroll
            for (int r = 0; r < 4; r++) s[nt][r] = 0.f;

        #pragma unroll
        for (int ks = 0; ks < 8; ks++) {
            unsigned bf[8][2];
            #pragma unroll
            for (int nt = 0; nt < 8; nt++) {
                bf[nt][0] = Kc[(nt * 8 + g) * SKS + ks * 8 + t4    ];
                bf[nt][1] = Kc[(nt * 8 + g) * SKS + ks * 8 + t4 + 4];
            }
            #pragma unroll
            for (int nt = 0; nt < 8; nt++) {
                mma_tf32(s[nt], qh[ks], bf[nt]);
                mma_tf32(s[nt], ql[ks], bf[nt]);
            }
        }

        // ---- online softmax -----------------------------------------------
        float mx0 = m0, mx1 = m1;
        #pragma unroll
        for (int nt = 0; nt < 8; nt++) {
            mx0 = fmaxf(mx0, fmaxf(s[nt][0], s[nt][1]));
            mx1 = fmaxf(mx1, fmaxf(s[nt][2], s[nt][3]));
        }
        mx0 = fmaxf(mx0, __shfl_xor_sync(0xffffffffu, mx0, 1));
        mx0 = fmaxf(mx0, __shfl_xor_sync(0xffffffffu, mx0, 2));
        mx1 = fmaxf(mx1, __shfl_xor_sync(0xffffffffu, mx1, 1));
        mx1 = fmaxf(mx1, __shfl_xor_sync(0xffffffffu, mx1, 2));

        float c0 = __expf(m0 - mx0);
        float c1 = __expf(m1 - mx1);
        m0 = mx0; m1 = mx1;

        float rs0 = 0.f, rs1 = 0.f;
        #pragma unroll
        for (int nt = 0; nt < 8; nt++) {
            float p0 = __expf(s[nt][0] - m0);
            float p1 = __expf(s[nt][1] - m0);
            float p2 = __expf(s[nt][2] - m1);
            float p3 = __expf(s[nt][3] - m1);
            rs0 += p0 + p1;
            rs1 += p2 + p3;
            Pw[(g    ) * SPS + nt * 8 + 2 * t4    ] = f2tf32(p0);
            Pw[(g    ) * SPS + nt * 8 + 2 * t4 + 1] = f2tf32(p1);
            Pw[(g + 8) * SPS + nt * 8 + 2 * t4    ] = f2tf32(p2);
            Pw[(g + 8) * SPS + nt * 8 + 2 * t4 + 1] = f2tf32(p3);
        }
        rs0 += __shfl_xor_sync(0xffffffffu, rs0, 1);
        rs0 += __shfl_xor_sync(0xffffffffu, rs0, 2);
        rs1 += __shfl_xor_sync(0xffffffffu, rs1, 1);
        rs1 += __shfl_xor_sync(0xffffffffu, rs1, 2);
        l0 = l0 * c0 + rs0;
        l1 = l1 * c1 + rs1;

        #pragma unroll
        for (int nt = 0; nt < 8; nt++) {
            out[nt][0] *= c0; out[nt][1] *= c0;
            out[nt][2] *= c1; out[nt][3] *= c1;
        }
        __syncwarp();

        // ---- out += P V ----------------------------------------------------
        #pragma unroll
        for (int ks = 0; ks < 8; ks++) {
            unsigned af[4];
            af[0] = Pw[(g    ) * SPS + ks * 8 + t4    ];
            af[1] = Pw[(g + 8) * SPS + ks * 8 + t4    ];
            af[2] = Pw[(g    ) * SPS + ks * 8 + t4 + 4];
            af[3] = Pw[(g + 8) * SPS + ks * 8 + t4 + 4];
            #pragma unroll
            for (int nt = 0; nt < 8; nt++) {
                unsigned bf2[2];
                bf2[0] = Vc[(ks * 8 + t4    ) * SVS + nt * 8 + g];
                bf2[1] = Vc[(ks * 8 + t4 + 4) * SVS + nt * 8 + g];
                mma_tf32(out[nt], af, bf2);
            }
        }

        if (more) {
            #pragma unroll
            for (int i = 0; i < 4; i++) {
                int f = tid + i * 256;
                int row = f >> 4, c4 = (f & 15) * 4;
                unsigned* p = &Kn[row * SKS + c4];
                p[0] = f2tf32(rk[i].x); p[1] = f2tf32(rk[i].y);
                p[2] = f2tf32(rk[i].z); p[3] = f2tf32(rk[i].w);
                unsigned* q = &Vn[row * SVS + c4];
                q[0] = f2tf32(rv[i].x); q[1] = f2tf32(rv[i].y);
                q[2] = f2tf32(rv[i].z); q[3] = f2tf32(rv[i].w);
            }
        }
        __syncthreads();
        unsigned* t;
        t = Kc; Kc = Kn; Kn = t;
        t = Vc; Vc = Vn; Vn = t;
    }

    // ---- epilogue: normalize, write to g_o in [B, N1, h*64+d] --------------
    float inv0 = 1.f / l0;
    float inv1 = 1.f / l1;
    int r0 = qb * ABR + wm + g;
    int r1 = r0 + 8;
    float* o0 = g_o + ((size_t)b * SEQ1 + r0) * INNER + h * DH;
    float* o1 = g_o + ((size_t)b * SEQ1 + r1) * INNER + h * DH;
    #pragma unroll
    for (int nt = 0; nt < 8; nt++) {
        int col = nt * 8 + 2 * t4;
        *(float2*)&o0[col] = make_float2(out[nt][0] * inv0, out[nt][1] * inv0);
        *(float2*)&o1[col] = make_float2(out[nt][2] * inv1, out[nt][3] * inv1);
    }
}

// ---------------- launch ----------------------------------------------------
extern "C" void kernel_launch(void* const* d_in, const int* in_sizes, int n_in,
                              void* d_out, int out_size)
{
    (void)in_sizes; (void)n_in; (void)out_size;
    const float* x1  = (const float*)d_in[0];
    const float* x2  = (const float*)d_in[1];
    const float* Wq1 = (const float*)d_in[2];
    const float* Wk1 = (const float*)d_in[3];
    const float* Wv1 = (const float*)d_in[4];
    const float* Wk2 = (const float*)d_in[5];
    const float* Wv2 = (const float*)d_in[6];
    const float* Wo  = (const float*)d_in[7];
    const float* bo  = (const float*)d_in[8];
    float* out = (float*)d_out;

    float *q, *k, *v, *o;
    cudaGetSymbolAddress((void**)&q, g_q);
    cudaGetSymbolAddress((void**)&k, g_k);
    cudaGetSymbolAddress((void**)&v, g_v);
    cudaGetSymbolAddress((void**)&o, g_o);

    static int attr_done = 0;
    if (!attr_done) {
        cudaFuncSetAttribute(proj_kernel, cudaFuncAttributeMaxDynamicSharedMemorySize, GEMM_SMEM);
        cudaFuncSetAttribute(out_kernel,  cudaFuncAttributeMaxDynamicSharedMemorySize, GEMM_SMEM);
        cudaFuncSetAttribute(attn_tc_kernel, cudaFuncAttributeMaxDynamicSharedMemorySize, ATTN_SMEM);
        attr_done = 1;
    }

    const int M = BATCH * SEQ1;   // 8192
    dim3 blk(256);

    proj_kernel<<<dim3(INNER / GBN, M / GBM, 5), blk, GEMM_SMEM>>>(
        x1, x2, Wq1, Wk1, Wv1, Wk2, Wv2, q, k, v);

    attn_tc_kernel<<<dim3(SEQ1 / ABR, HEADS, BATCH), blk, ATTN_SMEM>>>();

    out_kernel<<<dim3(DMODEL / GBN, M / GBM), blk, GEMM_SMEM>>>(o, Wo, bo, out);
}

// round 9
// speedup vs baseline: 4.2082x; 1.2571x over previous
#include <cuda_runtime.h>
#include <math.h>

#define HEADS  8
#define DH     64
#define BATCH  4
#define SEQ1   2048
#define NTOT   4096
#define DMODEL 1024
#define INNER  512

// ---------------- scratch (device globals; no allocations allowed) ----------
__device__ float g_q[(size_t)BATCH * HEADS * SEQ1 * DH];   // 16 MB
__device__ float g_k[(size_t)BATCH * HEADS * NTOT * DH];   // 32 MB
__device__ float g_v[(size_t)BATCH * HEADS * NTOT * DH];   // 32 MB
__device__ float g_o[(size_t)BATCH * SEQ1 * INNER];        // 16 MB

// ---------------- tf32 helpers ----------------------------------------------
__device__ __forceinline__ unsigned f2tf32(float f) {
    unsigned u;
    asm("cvt.rna.tf32.f32 %0, %1;" : "=r"(u) : "f"(f));
    return u;
}

__device__ __forceinline__ void mma_tf32(float* c, const unsigned* a, const unsigned* b) {
    asm volatile(
        "mma.sync.aligned.m16n8k8.row.col.f32.tf32.tf32.f32 "
        "{%0,%1,%2,%3}, {%4,%5,%6,%7}, {%8,%9}, {%0,%1,%2,%3};"
        : "+f"(c[0]), "+f"(c[1]), "+f"(c[2]), "+f"(c[3])
        : "r"(a[0]), "r"(a[1]), "r"(a[2]), "r"(a[3]), "r"(b[0]), "r"(b[1]));
}

// ---------------- tf32 GEMM core: C = A[M,K] @ W[K,N] (+bias) ---------------
// Block tile 128x128x32, 256 threads, single-buffer smem, 2 CTAs/SM
// (register-capped via launch_bounds; inter-CTA overlap hides load phases).
#define GBM 128
#define GBN 128
#define GBK 32
#define SA  36
#define SB  136
#define ASZ (GBM * SA)        // 4608 words
#define BSZ (GBK * SB)        // 4352 words
#define GEMM_SMEM ((ASZ + BSZ) * 4)   // 35840 B

template <bool HEAD_LAYOUT, bool BIAS>
__device__ __forceinline__ void gemm_core(
    const float* __restrict__ A, const float* __restrict__ W,
    const float* __restrict__ bias, float* __restrict__ C,
    int N, int K, int Ntot, int roff, unsigned* smu)
{
    unsigned* As = smu;
    unsigned* Bs = smu + ASZ;

    const int tid  = threadIdx.x;
    const int wid  = tid >> 5;
    const int lane = tid & 31;
    const int g    = lane >> 2;
    const int t4   = lane & 3;

    const int m0 = blockIdx.y * GBM;
    const int n0 = blockIdx.x * GBN;
    const int wm = (wid >> 2) * 64;
    const int wn = (wid & 3) * 32;

    float acc[4][4][4];
    #pragma unroll
    for (int i = 0; i < 4; i++)
        #pragma unroll
        for (int j = 0; j < 4; j++)
            #pragma unroll
            for (int r = 0; r < 4; r++) acc[i][j][r] = 0.f;

    const int T = K / GBK;

    for (int tIdx = 0; tIdx < T; tIdx++) {
        const int k0 = tIdx * GBK;
        if (tIdx) __syncthreads();    // protect smem before overwrite

        // load tile: LDG (batched first) then cvt+STS
        float4 ra[4], rb[4];
        #pragma unroll
        for (int i = 0; i < 4; i++) {
            int f = tid + i * 256;
            int row = f >> 3, kc = (f & 7) * 4;
            ra[i] = *(const float4*)(A + (size_t)(m0 + row) * K + k0 + kc);
            int kr = f >> 5, nc = (f & 31) * 4;
            rb[i] = *(const float4*)(W + (size_t)(k0 + kr) * N + n0 + nc);
        }
        #pragma unroll
        for (int i = 0; i < 4; i++) {
            int f = tid + i * 256;
            int row = f >> 3, kc = (f & 7) * 4;
            unsigned* p = &As[row * SA + kc];
            p[0] = f2tf32(ra[i].x); p[1] = f2tf32(ra[i].y);
            p[2] = f2tf32(ra[i].z); p[3] = f2tf32(ra[i].w);
            int kr = f >> 5, nc = (f & 31) * 4;
            unsigned* q = &Bs[kr * SB + nc];
            q[0] = f2tf32(rb[i].x); q[1] = f2tf32(rb[i].y);
            q[2] = f2tf32(rb[i].z); q[3] = f2tf32(rb[i].w);
        }
        __syncthreads();

        #pragma unroll
        for (int ks = 0; ks < 4; ks++) {
            int k = ks * 8;
            unsigned af[4][4], bf[4][2];
            #pragma unroll
            for (int mt = 0; mt < 4; mt++) {
                int r0 = wm + mt * 16 + g;
                af[mt][0] = As[(r0    ) * SA + k + t4];
                af[mt][1] = As[(r0 + 8) * SA + k + t4];
                af[mt][2] = As[(r0    ) * SA + k + t4 + 4];
                af[mt][3] = As[(r0 + 8) * SA + k + t4 + 4];
            }
            #pragma unroll
            for (int nt = 0; nt < 4; nt++) {
                int col = wn + nt * 8 + g;
                bf[nt][0] = Bs[(k + t4    ) * SB + col];
                bf[nt][1] = Bs[(k + t4 + 4) * SB + col];
            }
            #pragma unroll
            for (int mt = 0; mt < 4; mt++)
                #pragma unroll
                for (int nt = 0; nt < 4; nt++)
                    mma_tf32(acc[mt][nt], af[mt], bf[nt]);
        }
    }

    // epilogue
    #pragma unroll
    for (int mt = 0; mt < 4; mt++) {
        #pragma unroll
        for (int nt = 0; nt < 4; nt++) {
            int gm0 = m0 + wm + mt * 16 + g;
            int gn  = n0 + wn + nt * 8 + 2 * t4;
            float2 v0 = make_float2(acc[mt][nt][0], acc[mt][nt][1]);
            float2 v1 = make_float2(acc[mt][nt][2], acc[mt][nt][3]);
            if (BIAS) {
                float b0 = bias[gn], b1 = bias[gn + 1];
                v0.x += b0; v0.y += b1;
                v1.x += b0; v1.y += b1;
            }
            if (HEAD_LAYOUT) {
                int h = gn >> 6;
                int d = gn & 63;
                int b  = gm0 >> 11;
                int i0 = gm0 & (SEQ1 - 1);
                size_t base = (((size_t)b * HEADS + h) * Ntot + roff);
                *(float2*)&C[(base + i0) * DH + d]     = v0;
                *(float2*)&C[(base + i0 + 8) * DH + d] = v1;
            } else {
                *(float2*)&C[(size_t)gm0 * N + gn]       = v0;
                *(float2*)&C[(size_t)(gm0 + 8) * N + gn] = v1;
            }
        }
    }
}

// merged projection launch: grid.z selects which of the 5 GEMMs
__global__ __launch_bounds__(256, 2)
void proj_kernel(const float* __restrict__ x1, const float* __restrict__ x2,
                 const float* __restrict__ Wq1, const float* __restrict__ Wk1,
                 const float* __restrict__ Wv1, const float* __restrict__ Wk2,
                 const float* __restrict__ Wv2,
                 float* __restrict__ q, float* __restrict__ k, float* __restrict__ v)
{
    extern __shared__ unsigned smu[];
    const float* A; const float* W; float* C; int Ntot; int roff;
    switch (blockIdx.z) {
        case 0:  A = x1; W = Wq1; C = q; Ntot = SEQ1; roff = 0;    break;
        case 1:  A = x1; W = Wk1; C = k; Ntot = NTOT; roff = 0;    break;
        case 2:  A = x1; W = Wv1; C = v; Ntot = NTOT; roff = 0;    break;
        case 3:  A = x2; W = Wk2; C = k; Ntot = NTOT; roff = SEQ1; break;
        default: A = x2; W = Wv2; C = v; Ntot = NTOT; roff = SEQ1; break;
    }
    gemm_core<true, false>(A, W, nullptr, C, INNER, DMODEL, Ntot, roff, smu);
}

__global__ __launch_bounds__(256, 2)
void out_kernel(const float* __restrict__ A, const float* __restrict__ W,
                const float* __restrict__ bias, float* __restrict__ C)
{
    extern __shared__ unsigned smu[];
    gemm_core<false, true>(A, W, bias, C, DMODEL, INNER, 0, 0, smu);
}

// ---------------- tf32 tensor-core flash attention ---------------------------
// Br=128 q-rows per CTA (8 warps x 16 rows), Bc=64 kv per iteration.
// Single-buffer K/V smem, 2 CTAs/SM; Q single-pass tf32 (rna).
#define ABR 128
#define ABC 64
#define SKS 68
#define SVS 72
#define SPS 68
#define KSZ (64 * SKS)   // 4352 words
#define VSZ (64 * SVS)   // 4608 words
#define ATTN_SMEM ((KSZ + VSZ + 8 * 16 * SPS) * 4)   // 70656 B

__global__ __launch_bounds__(256, 2)
void attn_tc_kernel()
{
    extern __shared__ float sm[];
    unsigned* Ksu = (unsigned*)sm;
    unsigned* Vsu = (unsigned*)sm + KSZ;
    unsigned* Psu = (unsigned*)sm + KSZ + VSZ;

    const int tid  = threadIdx.x;
    const int wid  = tid >> 5;
    const int lane = tid & 31;
    const int g    = lane >> 2;
    const int t4   = lane & 3;
    const int wm   = wid * 16;

    const int qb = blockIdx.x, h = blockIdx.y, b = blockIdx.z;

    const float* Qg = g_q + (((size_t)b * HEADS + h) * SEQ1 + qb * ABR) * DH;
    const float* Kg = g_k + ((size_t)b * HEADS + h) * NTOT * DH;
    const float* Vg = g_v + ((size_t)b * HEADS + h) * NTOT * DH;

    // ---- stage Q into sm[0 .. 128*SKS) (aliases K/V buffers; freed below) --
    #pragma unroll
    for (int i = 0; i < 8; i++) {
        int f = tid + i * 256;
        int row = f >> 4, c4 = (f & 15) * 4;
        float4 v = *(const float4*)(Qg + row * DH + c4);
        float* p = sm + row * SKS + c4;
        p[0] = v.x; p[1] = v.y; p[2] = v.z; p[3] = v.w;
    }
    __syncthreads();

    // ---- extract Q a-frags (single rna pass), scaled -----------------------
    const float scale = 0.125f;
    unsigned qh[8][4];
    #pragma unroll
    for (int ks = 0; ks < 8; ks++) {
        int col = ks * 8 + t4;
        qh[ks][0] = f2tf32(sm[(wm + g    ) * SKS + col    ] * scale);
        qh[ks][1] = f2tf32(sm[(wm + g + 8) * SKS + col    ] * scale);
        qh[ks][2] = f2tf32(sm[(wm + g    ) * SKS + col + 4] * scale);
        qh[ks][3] = f2tf32(sm[(wm + g + 8) * SKS + col + 4] * scale);
    }
    __syncthreads();

    unsigned* Pw = Psu + wid * 16 * SPS;

    float out[8][4];
    #pragma unroll
    for (int nt = 0; nt < 8; nt++)
        #pragma unroll
        for (int r = 0; r < 4; r++) out[nt][r] = 0.f;

    float m0 = -INFINITY, m1 = -INFINITY, l0 = 0.f, l1 = 0.f;

    const int T = NTOT / ABC;

    for (int it = 0; it < T; it++) {
        if (it) __syncthreads();     // prior iteration's PV reads done

        // ---- load K,V tile (LDG batch, then cvt+STS) -----------------------
        const float* kt = Kg + (size_t)it * ABC * DH;
        const float* vt = Vg + (size_t)it * ABC * DH;
        float4 rk[4], rv[4];
        #pragma unroll
        for (int i = 0; i < 4; i++) {
            int f = tid + i * 256;
            int row = f >> 4, c4 = (f & 15) * 4;
            rk[i] = *(const float4*)(kt + row * DH + c4);
            rv[i] = *(const float4*)(vt + row * DH + c4);
        }
        #pragma unroll
        for (int i = 0; i < 4; i++) {
            int f = tid + i * 256;
            int row = f >> 4, c4 = (f & 15) * 4;
            unsigned* p = &Ksu[row * SKS + c4];
            p[0] = f2tf32(rk[i].x); p[1] = f2tf32(rk[i].y);
            p[2] = f2tf32(rk[i].z); p[3] = f2tf32(rk[i].w);
            unsigned* q = &Vsu[row * SVS + c4];
            q[0] = f2tf32(rv[i].x); q[1] = f2tf32(rv[i].y);
            q[2] = f2tf32(rv[i].z); q[3] = f2tf32(rv[i].w);
        }
        __syncthreads();

        // ---- S = Q K^T -----------------------------------------------------
        float s[8][4];
        #pragma unroll
        for (int nt = 0; nt < 8; nt++)
            #pragma unroll
            for (int r = 0; r < 4; r++) s[nt][r] = 0.f;

        #pragma unroll
        for (int ks = 0; ks < 8; ks++) {
            unsigned bf[8][2];
            #pragma unroll
            for (int nt = 0; nt < 8; nt++) {
                bf[nt][0] = Ksu[(nt * 8 + g) * SKS + ks * 8 + t4    ];
                bf[nt][1] = Ksu[(nt * 8 + g) * SKS + ks * 8 + t4 + 4];
            }
            #pragma unroll
            for (int nt = 0; nt < 8; nt++)
                mma_tf32(s[nt], qh[ks], bf[nt]);
        }

        // ---- online softmax -----------------------------------------------
        float mx0 = m0, mx1 = m1;
        #pragma unroll
        for (int nt = 0; nt < 8; nt++) {
            mx0 = fmaxf(mx0, fmaxf(s[nt][0], s[nt][1]));
            mx1 = fmaxf(mx1, fmaxf(s[nt][2], s[nt][3]));
        }
        mx0 = fmaxf(mx0, __shfl_xor_sync(0xffffffffu, mx0, 1));
        mx0 = fmaxf(mx0, __shfl_xor_sync(0xffffffffu, mx0, 2));
        mx1 = fmaxf(mx1, __shfl_xor_sync(0xffffffffu, mx1, 1));
        mx1 = fmaxf(mx1, __shfl_xor_sync(0xffffffffu, mx1, 2));

        float c0 = __expf(m0 - mx0);
        float c1 = __expf(m1 - mx1);
        m0 = mx0; m1 = mx1;

        float rs0 = 0.f, rs1 = 0.f;
        #pragma unroll
        for (int nt = 0; nt < 8; nt++) {
            float p0 = __expf(s[nt][0] - m0);
            float p1 = __expf(s[nt][1] - m0);
            float p2 = __expf(s[nt][2] - m1);
            float p3 = __expf(s[nt][3] - m1);
            rs0 += p0 + p1;
            rs1 += p2 + p3;
            Pw[(g    ) * SPS + nt * 8 + 2 * t4    ] = f2tf32(p0);
            Pw[(g    ) * SPS + nt * 8 + 2 * t4 + 1] = f2tf32(p1);
            Pw[(g + 8) * SPS + nt * 8 + 2 * t4    ] = f2tf32(p2);
            Pw[(g + 8) * SPS + nt * 8 + 2 * t4 + 1] = f2tf32(p3);
        }
        rs0 += __shfl_xor_sync(0xffffffffu, rs0, 1);
        rs0 += __shfl_xor_sync(0xffffffffu, rs0, 2);
        rs1 += __shfl_xor_sync(0xffffffffu, rs1, 1);
        rs1 += __shfl_xor_sync(0xffffffffu, rs1, 2);
        l0 = l0 * c0 + rs0;
        l1 = l1 * c1 + rs1;

        #pragma unroll
        for (int nt = 0; nt < 8; nt++) {
            out[nt][0] *= c0; out[nt][1] *= c0;
            out[nt][2] *= c1; out[nt][3] *= c1;
        }
        __syncwarp();

        // ---- out += P V ----------------------------------------------------
        #pragma unroll
        for (int ks = 0; ks < 8; ks++) {
            unsigned af[4];
            af[0] = Pw[(g    ) * SPS + ks * 8 + t4    ];
            af[1] = Pw[(g + 8) * SPS + ks * 8 + t4    ];
            af[2] = Pw[(g    ) * SPS + ks * 8 + t4 + 4];
            af[3] = Pw[(g + 8) * SPS + ks * 8 + t4 + 4];
            #pragma unroll
            for (int nt = 0; nt < 8; nt++) {
                unsigned bf2[2];
                bf2[0] = Vsu[(ks * 8 + t4    ) * SVS + nt * 8 + g];
                bf2[1] = Vsu[(ks * 8 + t4 + 4) * SVS + nt * 8 + g];
                mma_tf32(out[nt], af, bf2);
            }
        }
    }

    // ---- epilogue: normalize, write to g_o in [B, N1, h*64+d] --------------
    float inv0 = 1.f / l0;
    float inv1 = 1.f / l1;
    int r0 = qb * ABR + wm + g;
    int r1 = r0 + 8;
    float* o0 = g_o + ((size_t)b * SEQ1 + r0) * INNER + h * DH;
    float* o1 = g_o + ((size_t)b * SEQ1 + r1) * INNER + h * DH;
    #pragma unroll
    for (int nt = 0; nt < 8; nt++) {
        int col = nt * 8 + 2 * t4;
        *(float2*)&o0[col] = make_float2(out[nt][0] * inv0, out[nt][1] * inv0);
        *(float2*)&o1[col] = make_float2(out[nt][2] * inv1, out[nt][3] * inv1);
    }
}

// ---------------- launch ----------------------------------------------------
extern "C" void kernel_launch(void* const* d_in, const int* in_sizes, int n_in,
                              void* d_out, int out_size)
{
    (void)in_sizes; (void)n_in; (void)out_size;
    const float* x1  = (const float*)d_in[0];
    const float* x2  = (const float*)d_in[1];
    const float* Wq1 = (const float*)d_in[2];
    const float* Wk1 = (const float*)d_in[3];
    const float* Wv1 = (const float*)d_in[4];
    const float* Wk2 = (const float*)d_in[5];
    const float* Wv2 = (const float*)d_in[6];
    const float* Wo  = (const float*)d_in[7];
    const float* bo  = (const float*)d_in[8];
    float* out = (float*)d_out;

    float *q, *k, *v, *o;
    cudaGetSymbolAddress((void**)&q, g_q);
    cudaGetSymbolAddress((void**)&k, g_k);
    cudaGetSymbolAddress((void**)&v, g_v);
    cudaGetSymbolAddress((void**)&o, g_o);

    static int attr_done = 0;
    if (!attr_done) {
        cudaFuncSetAttribute(proj_kernel, cudaFuncAttributeMaxDynamicSharedMemorySize, GEMM_SMEM);
        cudaFuncSetAttribute(out_kernel,  cudaFuncAttributeMaxDynamicSharedMemorySize, GEMM_SMEM);
        cudaFuncSetAttribute(attn_tc_kernel, cudaFuncAttributeMaxDynamicSharedMemorySize, ATTN_SMEM);
        attr_done = 1;
    }

    const int M = BATCH * SEQ1;   // 8192
    dim3 blk(256);

    proj_kernel<<<dim3(INNER / GBN, M / GBM, 5), blk, GEMM_SMEM>>>(
        x1, x2, Wq1, Wk1, Wv1, Wk2, Wv2, q, k, v);

    attn_tc_kernel<<<dim3(SEQ1 / ABR, HEADS, BATCH), blk, ATTN_SMEM>>>();

    out_kernel<<<dim3(DMODEL / GBN, M / GBM), blk, GEMM_SMEM>>>(o, Wo, bo, out);
}

// round 10
// speedup vs baseline: 4.3516x; 1.0341x over previous
#include <cuda_runtime.h>
#include <math.h>

#define HEADS  8
#define DH     64
#define BATCH  4
#define SEQ1   2048
#define NTOT   4096
#define DMODEL 1024
#define INNER  512

// ---------------- scratch (device globals; no allocations allowed) ----------
__device__ float g_q[(size_t)BATCH * HEADS * SEQ1 * DH];   // 16 MB
__device__ float g_k[(size_t)BATCH * HEADS * NTOT * DH];   // 32 MB
__device__ float g_v[(size_t)BATCH * HEADS * NTOT * DH];   // 32 MB
__device__ float g_o[(size_t)BATCH * SEQ1 * INNER];        // 16 MB

// ---------------- tf32 helpers ----------------------------------------------
__device__ __forceinline__ unsigned f2tf32(float f) {
    unsigned u;
    asm("cvt.rna.tf32.f32 %0, %1;" : "=r"(u) : "f"(f));
    return u;
}

__device__ __forceinline__ void mma_tf32(float* c, const unsigned* a, const unsigned* b) {
    asm volatile(
        "mma.sync.aligned.m16n8k8.row.col.f32.tf32.tf32.f32 "
        "{%0,%1,%2,%3}, {%4,%5,%6,%7}, {%8,%9}, {%0,%1,%2,%3};"
        : "+f"(c[0]), "+f"(c[1]), "+f"(c[2]), "+f"(c[3])
        : "r"(a[0]), "r"(a[1]), "r"(a[2]), "r"(a[3]), "r"(b[0]), "r"(b[1]));
}

// ---------------- tf32 GEMM core: C = A[M,K] @ W[K,N] (+bias) ---------------
// Block tile 128x128x32, 128 threads = 4 warps, warp tile 64x64.
// 2 CTAs/SM (launch_bounds 128,2 -> 256-reg budget). Crossbar traffic per MMA
// reduced 1.5x vs 64x32 warp tiles.
#define GBM 128
#define GBN 128
#define GBK 32
#define SA  36
#define SB  136
#define ASZ (GBM * SA)        // 4608 words
#define BSZ (GBK * SB)        // 4352 words
#define GEMM_SMEM ((ASZ + BSZ) * 4)   // 35840 B

template <bool HEAD_LAYOUT, bool BIAS>
__device__ __forceinline__ void gemm_core(
    const float* __restrict__ A, const float* __restrict__ W,
    const float* __restrict__ bias, float* __restrict__ C,
    int N, int K, int Ntot, int roff, unsigned* smu)
{
    unsigned* As = smu;
    unsigned* Bs = smu + ASZ;

    const int tid  = threadIdx.x;
    const int wid  = tid >> 5;
    const int lane = tid & 31;
    const int g    = lane >> 2;
    const int t4   = lane & 3;

    const int m0 = blockIdx.y * GBM;
    const int n0 = blockIdx.x * GBN;
    const int wm = (wid >> 1) * 64;   // 0 or 64
    const int wn = (wid & 1) * 64;    // 0 or 64

    float acc[4][8][4];
    #pragma unroll
    for (int i = 0; i < 4; i++)
        #pragma unroll
        for (int j = 0; j < 8; j++)
            #pragma unroll
            for (int r = 0; r < 4; r++) acc[i][j][r] = 0.f;

    const int T = K / GBK;

    for (int tIdx = 0; tIdx < T; tIdx++) {
        const int k0 = tIdx * GBK;
        if (tIdx) __syncthreads();    // protect smem before overwrite

        // A tile: 128x32 = 1024 f4, 8 per thread
        {
            float4 ra[8];
            #pragma unroll
            for (int i = 0; i < 8; i++) {
                int f = tid + i * 128;
                int row = f >> 3, kc = (f & 7) * 4;
                ra[i] = *(const float4*)(A + (size_t)(m0 + row) * K + k0 + kc);
            }
            #pragma unroll
            for (int i = 0; i < 8; i++) {
                int f = tid + i * 128;
                int row = f >> 3, kc = (f & 7) * 4;
                unsigned* p = &As[row * SA + kc];
                p[0] = f2tf32(ra[i].x); p[1] = f2tf32(ra[i].y);
                p[2] = f2tf32(ra[i].z); p[3] = f2tf32(ra[i].w);
            }
        }
        // B tile: 32x128 = 1024 f4, 8 per thread
        {
            float4 rb[8];
            #pragma unroll
            for (int i = 0; i < 8; i++) {
                int f = tid + i * 128;
                int kr = f >> 5, nc = (f & 31) * 4;
                rb[i] = *(const float4*)(W + (size_t)(k0 + kr) * N + n0 + nc);
            }
            #pragma unroll
            for (int i = 0; i < 8; i++) {
                int f = tid + i * 128;
                int kr = f >> 5, nc = (f & 31) * 4;
                unsigned* q = &Bs[kr * SB + nc];
                q[0] = f2tf32(rb[i].x); q[1] = f2tf32(rb[i].y);
                q[2] = f2tf32(rb[i].z); q[3] = f2tf32(rb[i].w);
            }
        }
        __syncthreads();

        #pragma unroll
        for (int ks = 0; ks < 4; ks++) {
            int k = ks * 8;
            unsigned af[4][4];
            #pragma unroll
            for (int mt = 0; mt < 4; mt++) {
                int r0 = wm + mt * 16 + g;
                af[mt][0] = As[(r0    ) * SA + k + t4];
                af[mt][1] = As[(r0 + 8) * SA + k + t4];
                af[mt][2] = As[(r0    ) * SA + k + t4 + 4];
                af[mt][3] = As[(r0 + 8) * SA + k + t4 + 4];
            }
            #pragma unroll
            for (int nt = 0; nt < 8; nt++) {
                int col = wn + nt * 8 + g;
                unsigned bf[2];
                bf[0] = Bs[(k + t4    ) * SB + col];
                bf[1] = Bs[(k + t4 + 4) * SB + col];
                #pragma unroll
                for (int mt = 0; mt < 4; mt++)
                    mma_tf32(acc[mt][nt], af[mt], bf);
            }
        }
    }

    // epilogue
    #pragma unroll
    for (int mt = 0; mt < 4; mt++) {
        #pragma unroll
        for (int nt = 0; nt < 8; nt++) {
            int gm0 = m0 + wm + mt * 16 + g;
            int gn  = n0 + wn + nt * 8 + 2 * t4;
            float2 v0 = make_float2(acc[mt][nt][0], acc[mt][nt][1]);
            float2 v1 = make_float2(acc[mt][nt][2], acc[mt][nt][3]);
            if (BIAS) {
                float b0 = bias[gn], b1 = bias[gn + 1];
                v0.x += b0; v0.y += b1;
                v1.x += b0; v1.y += b1;
            }
            if (HEAD_LAYOUT) {
                int h = gn >> 6;
                int d = gn & 63;
                int b  = gm0 >> 11;
                int i0 = gm0 & (SEQ1 - 1);
                size_t base = (((size_t)b * HEADS + h) * Ntot + roff);
                *(float2*)&C[(base + i0) * DH + d]     = v0;
                *(float2*)&C[(base + i0 + 8) * DH + d] = v1;
            } else {
                *(float2*)&C[(size_t)gm0 * N + gn]       = v0;
                *(float2*)&C[(size_t)(gm0 + 8) * N + gn] = v1;
            }
        }
    }
}

// merged projection launch: grid.z selects which of the 5 GEMMs
__global__ __launch_bounds__(128, 2)
void proj_kernel(const float* __restrict__ x1, const float* __restrict__ x2,
                 const float* __restrict__ Wq1, const float* __restrict__ Wk1,
                 const float* __restrict__ Wv1, const float* __restrict__ Wk2,
                 const float* __restrict__ Wv2,
                 float* __restrict__ q, float* __restrict__ k, float* __restrict__ v)
{
    extern __shared__ unsigned smu[];
    const float* A; const float* W; float* C; int Ntot; int roff;
    switch (blockIdx.z) {
        case 0:  A = x1; W = Wq1; C = q; Ntot = SEQ1; roff = 0;    break;
        case 1:  A = x1; W = Wk1; C = k; Ntot = NTOT; roff = 0;    break;
        case 2:  A = x1; W = Wv1; C = v; Ntot = NTOT; roff = 0;    break;
        case 3:  A = x2; W = Wk2; C = k; Ntot = NTOT; roff = SEQ1; break;
        default: A = x2; W = Wv2; C = v; Ntot = NTOT; roff = SEQ1; break;
    }
    gemm_core<true, false>(A, W, nullptr, C, INNER, DMODEL, Ntot, roff, smu);
}

__global__ __launch_bounds__(128, 2)
void out_kernel(const float* __restrict__ A, const float* __restrict__ W,
                const float* __restrict__ bias, float* __restrict__ C)
{
    extern __shared__ unsigned smu[];
    gemm_core<false, true>(A, W, bias, C, DMODEL, INNER, 0, 0, smu);
}

// ---------------- tf32 tensor-core flash attention ---------------------------
// 128 threads = 4 warps; warp owns 32 q-rows (2 m-frags); Bc=64 kv/iter.
// K/V fragments amortized over 2 m-frags -> ~1.8x less LDS per MMA.
#define ABR 128
#define ABC 64
#define SKS 68
#define SVS 72
#define SPS 68
#define KSZ (64 * SKS)   // 4352 words
#define VSZ (64 * SVS)   // 4608 words
#define PSZ (128 * SPS)  // 8704 words (4 warps x 32 rows)
#define ATTN_SMEM ((KSZ + VSZ + PSZ) * 4)   // 70656 B

__global__ __launch_bounds__(128, 2)
void attn_tc_kernel()
{
    extern __shared__ float sm[];
    unsigned* Ksu = (unsigned*)sm;
    unsigned* Vsu = (unsigned*)sm + KSZ;
    unsigned* Psu = (unsigned*)sm + KSZ + VSZ;

    const int tid  = threadIdx.x;
    const int wid  = tid >> 5;
    const int lane = tid & 31;
    const int g    = lane >> 2;
    const int t4   = lane & 3;
    const int wm   = wid * 32;

    const int qb = blockIdx.x, h = blockIdx.y, b = blockIdx.z;

    const float* Qg = g_q + (((size_t)b * HEADS + h) * SEQ1 + qb * ABR) * DH;
    const float* Kg = g_k + ((size_t)b * HEADS + h) * NTOT * DH;
    const float* Vg = g_v + ((size_t)b * HEADS + h) * NTOT * DH;

    // ---- stage Q into sm[0 .. 128*SKS) (aliases K/V buffers; freed below) --
    #pragma unroll
    for (int i = 0; i < 16; i++) {
        int f = tid + i * 128;
        int row = f >> 4, c4 = (f & 15) * 4;
        float4 v = *(const float4*)(Qg + row * DH + c4);
        float* p = sm + row * SKS + c4;
        p[0] = v.x; p[1] = v.y; p[2] = v.z; p[3] = v.w;
    }
    __syncthreads();

    // ---- extract Q a-frags (2 m-frags, single rna pass), scaled ------------
    const float scale = 0.125f;
    unsigned qh[2][8][4];
    #pragma unroll
    for (int mt = 0; mt < 2; mt++) {
        int r0 = wm + mt * 16 + g;
        #pragma unroll
        for (int ks = 0; ks < 8; ks++) {
            int col = ks * 8 + t4;
            qh[mt][ks][0] = f2tf32(sm[(r0    ) * SKS + col    ] * scale);
            qh[mt][ks][1] = f2tf32(sm[(r0 + 8) * SKS + col    ] * scale);
            qh[mt][ks][2] = f2tf32(sm[(r0    ) * SKS + col + 4] * scale);
            qh[mt][ks][3] = f2tf32(sm[(r0 + 8) * SKS + col + 4] * scale);
        }
    }
    __syncthreads();

    unsigned* Pw = Psu + wid * 32 * SPS;

    float out[2][8][4];
    #pragma unroll
    for (int mt = 0; mt < 2; mt++)
        #pragma unroll
        for (int nt = 0; nt < 8; nt++)
            #pragma unroll
            for (int r = 0; r < 4; r++) out[mt][nt][r] = 0.f;

    float mA[2][2], lA[2][2];
    #pragma unroll
    for (int mt = 0; mt < 2; mt++) {
        mA[mt][0] = -INFINITY; mA[mt][1] = -INFINITY;
        lA[mt][0] = 0.f;       lA[mt][1] = 0.f;
    }

    const int T = NTOT / ABC;

    for (int it = 0; it < T; it++) {
        if (it) __syncthreads();     // prior iteration's PV reads done

        // ---- load K,V tile (LDG batch, then cvt+STS) -----------------------
        const float* kt = Kg + (size_t)it * ABC * DH;
        const float* vt = Vg + (size_t)it * ABC * DH;
        float4 rk[8], rv[8];
        #pragma unroll
        for (int i = 0; i < 8; i++) {
            int f = tid + i * 128;
            int row = f >> 4, c4 = (f & 15) * 4;
            rk[i] = *(const float4*)(kt + row * DH + c4);
            rv[i] = *(const float4*)(vt + row * DH + c4);
        }
        #pragma unroll
        for (int i = 0; i < 8; i++) {
            int f = tid + i * 128;
            int row = f >> 4, c4 = (f & 15) * 4;
            unsigned* p = &Ksu[row * SKS + c4];
            p[0] = f2tf32(rk[i].x); p[1] = f2tf32(rk[i].y);
            p[2] = f2tf32(rk[i].z); p[3] = f2tf32(rk[i].w);
            unsigned* q = &Vsu[row * SVS + c4];
            q[0] = f2tf32(rv[i].x); q[1] = f2tf32(rv[i].y);
            q[2] = f2tf32(rv[i].z); q[3] = f2tf32(rv[i].w);
        }
        __syncthreads();

        // ---- S = Q K^T (K-frags shared across both m-frags) ----------------
        float s[2][8][4];
        #pragma unroll
        for (int mt = 0; mt < 2; mt++)
            #pragma unroll
            for (int nt = 0; nt < 8; nt++)
                #pragma unroll
                for (int r = 0; r < 4; r++) s[mt][nt][r] = 0.f;

        #pragma unroll
        for (int ks = 0; ks < 8; ks++) {
            #pragma unroll
            for (int nt = 0; nt < 8; nt++) {
                unsigned bf[2];
                bf[0] = Ksu[(nt * 8 + g) * SKS + ks * 8 + t4    ];
                bf[1] = Ksu[(nt * 8 + g) * SKS + ks * 8 + t4 + 4];
                mma_tf32(s[0][nt], qh[0][ks], bf);
                mma_tf32(s[1][nt], qh[1][ks], bf);
            }
        }

        // ---- online softmax (per m-frag) ----------------------------------
        #pragma unroll
        for (int mt = 0; mt < 2; mt++) {
            float mx0 = mA[mt][0], mx1 = mA[mt][1];
            #pragma unroll
            for (int nt = 0; nt < 8; nt++) {
                mx0 = fmaxf(mx0, fmaxf(s[mt][nt][0], s[mt][nt][1]));
                mx1 = fmaxf(mx1, fmaxf(s[mt][nt][2], s[mt][nt][3]));
            }
            mx0 = fmaxf(mx0, __shfl_xor_sync(0xffffffffu, mx0, 1));
            mx0 = fmaxf(mx0, __shfl_xor_sync(0xffffffffu, mx0, 2));
            mx1 = fmaxf(mx1, __shfl_xor_sync(0xffffffffu, mx1, 1));
            mx1 = fmaxf(mx1, __shfl_xor_sync(0xffffffffu, mx1, 2));

            float c0 = __expf(mA[mt][0] - mx0);
            float c1 = __expf(mA[mt][1] - mx1);
            mA[mt][0] = mx0; mA[mt][1] = mx1;

            float rs0 = 0.f, rs1 = 0.f;
            #pragma unroll
            for (int nt = 0; nt < 8; nt++) {
                float p0 = __expf(s[mt][nt][0] - mx0);
                float p1 = __expf(s[mt][nt][1] - mx0);
                float p2 = __expf(s[mt][nt][2] - mx1);
                float p3 = __expf(s[mt][nt][3] - mx1);
                rs0 += p0 + p1;
                rs1 += p2 + p3;
                int r0 = mt * 16 + g;
                Pw[(r0    ) * SPS + nt * 8 + 2 * t4    ] = f2tf32(p0);
                Pw[(r0    ) * SPS + nt * 8 + 2 * t4 + 1] = f2tf32(p1);
                Pw[(r0 + 8) * SPS + nt * 8 + 2 * t4    ] = f2tf32(p2);
                Pw[(r0 + 8) * SPS + nt * 8 + 2 * t4 + 1] = f2tf32(p3);
            }
            rs0 += __shfl_xor_sync(0xffffffffu, rs0, 1);
            rs0 += __shfl_xor_sync(0xffffffffu, rs0, 2);
            rs1 += __shfl_xor_sync(0xffffffffu, rs1, 1);
            rs1 += __shfl_xor_sync(0xffffffffu, rs1, 2);
            lA[mt][0] = lA[mt][0] * c0 + rs0;
            lA[mt][1] = lA[mt][1] * c1 + rs1;

            #pragma unroll
            for (int nt = 0; nt < 8; nt++) {
                out[mt][nt][0] *= c0; out[mt][nt][1] *= c0;
                out[mt][nt][2] *= c1; out[mt][nt][3] *= c1;
            }
        }
        __syncwarp();

        // ---- out += P V (V-frags shared across both m-frags) ---------------
        #pragma unroll
        for (int ks = 0; ks < 8; ks++) {
            unsigned af[2][4];
            #pragma unroll
            for (int mt = 0; mt < 2; mt++) {
                int r0 = mt * 16 + g;
                af[mt][0] = Pw[(r0    ) * SPS + ks * 8 + t4    ];
                af[mt][1] = Pw[(r0 + 8) * SPS + ks * 8 + t4    ];
                af[mt][2] = Pw[(r0    ) * SPS + ks * 8 + t4 + 4];
                af[mt][3] = Pw[(r0 + 8) * SPS + ks * 8 + t4 + 4];
            }
            #pragma unroll
            for (int nt = 0; nt < 8; nt++) {
                unsigned bf2[2];
                bf2[0] = Vsu[(ks * 8 + t4    ) * SVS + nt * 8 + g];
                bf2[1] = Vsu[(ks * 8 + t4 + 4) * SVS + nt * 8 + g];
                mma_tf32(out[0][nt], af[0], bf2);
                mma_tf32(out[1][nt], af[1], bf2);
            }
        }
    }

    // ---- epilogue: normalize, write to g_o in [B, N1, h*64+d] --------------
    #pragma unroll
    for (int mt = 0; mt < 2; mt++) {
        float inv0 = 1.f / lA[mt][0];
        float inv1 = 1.f / lA[mt][1];
        int r0 = qb * ABR + wm + mt * 16 + g;
        int r1 = r0 + 8;
        float* o0 = g_o + ((size_t)b * SEQ1 + r0) * INNER + h * DH;
        float* o1 = g_o + ((size_t)b * SEQ1 + r1) * INNER + h * DH;
        #pragma unroll
        for (int nt = 0; nt < 8; nt++) {
            int col = nt * 8 + 2 * t4;
            *(float2*)&o0[col] = make_float2(out[mt][nt][0] * inv0, out[mt][nt][1] * inv0);
            *(float2*)&o1[col] = make_float2(out[mt][nt][2] * inv1, out[mt][nt][3] * inv1);
        }
    }
}

// ---------------- launch ----------------------------------------------------
extern "C" void kernel_launch(void* const* d_in, const int* in_sizes, int n_in,
                              void* d_out, int out_size)
{
    (void)in_sizes; (void)n_in; (void)out_size;
    const float* x1  = (const float*)d_in[0];
    const float* x2  = (const float*)d_in[1];
    const float* Wq1 = (const float*)d_in[2];
    const float* Wk1 = (const float*)d_in[3];
    const float* Wv1 = (const float*)d_in[4];
    const float* Wk2 = (const float*)d_in[5];
    const float* Wv2 = (const float*)d_in[6];
    const float* Wo  = (const float*)d_in[7];
    const float* bo  = (const float*)d_in[8];
    float* out = (float*)d_out;

    float *q, *k, *v, *o;
    cudaGetSymbolAddress((void**)&q, g_q);
    cudaGetSymbolAddress((void**)&k, g_k);
    cudaGetSymbolAddress((void**)&v, g_v);
    cudaGetSymbolAddress((void**)&o, g_o);

    static int attr_done = 0;
    if (!attr_done) {
        cudaFuncSetAttribute(proj_kernel, cudaFuncAttributeMaxDynamicSharedMemorySize, GEMM_SMEM);
        cudaFuncSetAttribute(out_kernel,  cudaFuncAttributeMaxDynamicSharedMemorySize, GEMM_SMEM);
        cudaFuncSetAttribute(attn_tc_kernel, cudaFuncAttributeMaxDynamicSharedMemorySize, ATTN_SMEM);
        attr_done = 1;
    }

    const int M = BATCH * SEQ1;   // 8192
    dim3 blk(128);

    proj_kernel<<<dim3(INNER / GBN, M / GBM, 5), blk, GEMM_SMEM>>>(
        x1, x2, Wq1, Wk1, Wv1, Wk2, Wv2, q, k, v);

    attn_tc_kernel<<<dim3(SEQ1 / ABR, HEADS, BATCH), blk, ATTN_SMEM>>>();

    out_kernel<<<dim3(DMODEL / GBN, M / GBM), blk, GEMM_SMEM>>>(o, Wo, bo, out);
}

// round 14
// speedup vs baseline: 4.4712x; 1.0275x over previous
#include <cuda_runtime.h>
#include <math.h>

#define HEADS  8
#define DH     64
#define BATCH  4
#define SEQ1   2048
#define NTOT   4096
#define DMODEL 1024
#define INNER  512

// ---------------- scratch (device globals; no allocations allowed) ----------
__device__ float g_q[(size_t)BATCH * HEADS * SEQ1 * DH];   // 16 MB
__device__ float g_k[(size_t)BATCH * HEADS * NTOT * DH];   // 32 MB
__device__ float g_v[(size_t)BATCH * HEADS * NTOT * DH];   // 32 MB
__device__ float g_o[(size_t)BATCH * SEQ1 * INNER];        // 16 MB

// ---------------- tf32 helpers ----------------------------------------------
__device__ __forceinline__ unsigned f2tf32(float f) {
    unsigned u;
    asm("cvt.rna.tf32.f32 %0, %1;" : "=r"(u) : "f"(f));
    return u;
}

__device__ __forceinline__ void mma_tf32(float* c, const unsigned* a, const unsigned* b) {
    asm volatile(
        "mma.sync.aligned.m16n8k8.row.col.f32.tf32.tf32.f32 "
        "{%0,%1,%2,%3}, {%4,%5,%6,%7}, {%8,%9}, {%0,%1,%2,%3};"
        : "+f"(c[0]), "+f"(c[1]), "+f"(c[2]), "+f"(c[3])
        : "r"(a[0]), "r"(a[1]), "r"(a[2]), "r"(a[3]), "r"(b[0]), "r"(b[1]));
}

// ---------------- tf32 GEMM core: C = A[M,K] @ W[K,N] (+bias) ---------------
// Block tile 128x128x32, 256 threads = 8 warps, warp tile 64x32.
// 2 CTAs/SM via launch_bounds(256,2); inter-CTA overlap hides load phases.
// (Round-9 proven config: 283us/proj, tensor=49.9%.)
#define GBM 128
#define GBN 128
#define GBK 32
#define SA  36
#define SB  136
#define ASZ (GBM * SA)        // 4608 words
#define BSZ (GBK * SB)        // 4352 words
#define GEMM_SMEM ((ASZ + BSZ) * 4)   // 35840 B

template <bool HEAD_LAYOUT, bool BIAS>
__device__ __forceinline__ void gemm_core(
    const float* __restrict__ A, const float* __restrict__ W,
    const float* __restrict__ bias, float* __restrict__ C,
    int N, int K, int Ntot, int roff, unsigned* smu)
{
    unsigned* As = smu;
    unsigned* Bs = smu + ASZ;

    const int tid  = threadIdx.x;
    const int wid  = tid >> 5;
    const int lane = tid & 31;
    const int g    = lane >> 2;
    const int t4   = lane & 3;

    const int m0 = blockIdx.y * GBM;
    const int n0 = blockIdx.x * GBN;
    const int wm = (wid >> 2) * 64;
    const int wn = (wid & 3) * 32;

    float acc[4][4][4];
    #pragma unroll
    for (int i = 0; i < 4; i++)
        #pragma unroll
        for (int j = 0; j < 4; j++)
            #pragma unroll
            for (int r = 0; r < 4; r++) acc[i][j][r] = 0.f;

    const int T = K / GBK;

    for (int tIdx = 0; tIdx < T; tIdx++) {
        const int k0 = tIdx * GBK;
        if (tIdx) __syncthreads();    // protect smem before overwrite

        // load tile: LDG (batched first) then cvt+STS
        float4 ra[4], rb[4];
        #pragma unroll
        for (int i = 0; i < 4; i++) {
            int f = tid + i * 256;
            int row = f >> 3, kc = (f & 7) * 4;
            ra[i] = *(const float4*)(A + (size_t)(m0 + row) * K + k0 + kc);
            int kr = f >> 5, nc = (f & 31) * 4;
            rb[i] = *(const float4*)(W + (size_t)(k0 + kr) * N + n0 + nc);
        }
        #pragma unroll
        for (int i = 0; i < 4; i++) {
            int f = tid + i * 256;
            int row = f >> 3, kc = (f & 7) * 4;
            unsigned* p = &As[row * SA + kc];
            p[0] = f2tf32(ra[i].x); p[1] = f2tf32(ra[i].y);
            p[2] = f2tf32(ra[i].z); p[3] = f2tf32(ra[i].w);
            int kr = f >> 5, nc = (f & 31) * 4;
            unsigned* q = &Bs[kr * SB + nc];
            q[0] = f2tf32(rb[i].x); q[1] = f2tf32(rb[i].y);
            q[2] = f2tf32(rb[i].z); q[3] = f2tf32(rb[i].w);
        }
        __syncthreads();

        #pragma unroll
        for (int ks = 0; ks < 4; ks++) {
            int k = ks * 8;
            unsigned af[4][4], bf[4][2];
            #pragma unroll
            for (int mt = 0; mt < 4; mt++) {
                int r0 = wm + mt * 16 + g;
                af[mt][0] = As[(r0    ) * SA + k + t4];
                af[mt][1] = As[(r0 + 8) * SA + k + t4];
                af[mt][2] = As[(r0    ) * SA + k + t4 + 4];
                af[mt][3] = As[(r0 + 8) * SA + k + t4 + 4];
            }
            #pragma unroll
            for (int nt = 0; nt < 4; nt++) {
                int col = wn + nt * 8 + g;
                bf[nt][0] = Bs[(k + t4    ) * SB + col];
                bf[nt][1] = Bs[(k + t4 + 4) * SB + col];
            }
            #pragma unroll
            for (int mt = 0; mt < 4; mt++)
                #pragma unroll
                for (int nt = 0; nt < 4; nt++)
                    mma_tf32(acc[mt][nt], af[mt], bf[nt]);
        }
    }

    // epilogue
    #pragma unroll
    for (int mt = 0; mt < 4; mt++) {
        #pragma unroll
        for (int nt = 0; nt < 4; nt++) {
            int gm0 = m0 + wm + mt * 16 + g;
            int gn  = n0 + wn + nt * 8 + 2 * t4;
            float2 v0 = make_float2(acc[mt][nt][0], acc[mt][nt][1]);
            float2 v1 = make_float2(acc[mt][nt][2], acc[mt][nt][3]);
            if (BIAS) {
                float b0 = bias[gn], b1 = bias[gn + 1];
                v0.x += b0; v0.y += b1;
                v1.x += b0; v1.y += b1;
            }
            if (HEAD_LAYOUT) {
                int h = gn >> 6;
                int d = gn & 63;
                int b  = gm0 >> 11;
                int i0 = gm0 & (SEQ1 - 1);
                size_t base = (((size_t)b * HEADS + h) * Ntot + roff);
                *(float2*)&C[(base + i0) * DH + d]     = v0;
                *(float2*)&C[(base + i0 + 8) * DH + d] = v1;
            } else {
                *(float2*)&C[(size_t)gm0 * N + gn]       = v0;
                *(float2*)&C[(size_t)(gm0 + 8) * N + gn] = v1;
            }
        }
    }
}

// merged projection launch: grid.z selects which of the 5 GEMMs
__global__ __launch_bounds__(256, 2)
void proj_kernel(const float* __restrict__ x1, const float* __restrict__ x2,
                 const float* __restrict__ Wq1, const float* __restrict__ Wk1,
                 const float* __restrict__ Wv1, const float* __restrict__ Wk2,
                 const float* __restrict__ Wv2,
                 float* __restrict__ q, float* __restrict__ k, float* __restrict__ v)
{
    extern __shared__ unsigned smu[];
    const float* A; const float* W; float* C; int Ntot; int roff;
    switch (blockIdx.z) {
        case 0:  A = x1; W = Wq1; C = q; Ntot = SEQ1; roff = 0;    break;
        case 1:  A = x1; W = Wk1; C = k; Ntot = NTOT; roff = 0;    break;
        case 2:  A = x1; W = Wv1; C = v; Ntot = NTOT; roff = 0;    break;
        case 3:  A = x2; W = Wk2; C = k; Ntot = NTOT; roff = SEQ1; break;
        default: A = x2; W = Wv2; C = v; Ntot = NTOT; roff = SEQ1; break;
    }
    gemm_core<true, false>(A, W, nullptr, C, INNER, DMODEL, Ntot, roff, smu);
}

__global__ __launch_bounds__(256, 2)
void out_kernel(const float* __restrict__ A, const float* __restrict__ W,
                const float* __restrict__ bias, float* __restrict__ C)
{
    extern __shared__ unsigned smu[];
    gemm_core<false, true>(A, W, bias, C, DMODEL, INNER, 0, 0, smu);
}

// ---------------- tf32 tensor-core flash attention ---------------------------
// 128 threads = 4 warps; warp owns 32 q-rows (2 m-frags); Bc=64 kv/iter.
// K/V frags amortized over 2 m-frags. Fused LDG->cvt->STS tile load (no
// staging arrays) to stay under the 256-reg cap without spills.
#define ABR 128
#define ABC 64
#define SKS 68
#define SVS 72
#define SPS 68
#define KSZ (64 * SKS)   // 4352 words
#define VSZ (64 * SVS)   // 4608 words
#define PSZ (128 * SPS)  // 8704 words (4 warps x 32 rows)
#define ATTN_SMEM ((KSZ + VSZ + PSZ) * 4)   // 70656 B

__global__ __launch_bounds__(128, 2)
void attn_tc_kernel()
{
    extern __shared__ float sm[];
    unsigned* Ksu = (unsigned*)sm;
    unsigned* Vsu = (unsigned*)sm + KSZ;
    unsigned* Psu = (unsigned*)sm + KSZ + VSZ;

    const int tid  = threadIdx.x;
    const int wid  = tid >> 5;
    const int lane = tid & 31;
    const int g    = lane >> 2;
    const int t4   = lane & 3;
    const int wm   = wid * 32;

    const int qb = blockIdx.x, h = blockIdx.y, b = blockIdx.z;

    const float* Qg = g_q + (((size_t)b * HEADS + h) * SEQ1 + qb * ABR) * DH;
    const float* Kg = g_k + ((size_t)b * HEADS + h) * NTOT * DH;
    const float* Vg = g_v + ((size_t)b * HEADS + h) * NTOT * DH;

    // ---- stage Q into sm[0 .. 128*SKS) (aliases K/V buffers; freed below) --
    #pragma unroll
    for (int i = 0; i < 16; i++) {
        int f = tid + i * 128;
        int row = f >> 4, c4 = (f & 15) * 4;
        float4 v = *(const float4*)(Qg + row * DH + c4);
        float* p = sm + row * SKS + c4;
        p[0] = v.x; p[1] = v.y; p[2] = v.z; p[3] = v.w;
    }
    __syncthreads();

    // ---- extract Q a-frags (2 m-frags, single rna pass), scaled ------------
    const float scale = 0.125f;
    unsigned qh[2][8][4];
    #pragma unroll
    for (int mt = 0; mt < 2; mt++) {
        int r0 = wm + mt * 16 + g;
        #pragma unroll
        for (int ks = 0; ks < 8; ks++) {
            int col = ks * 8 + t4;
            qh[mt][ks][0] = f2tf32(sm[(r0    ) * SKS + col    ] * scale);
            qh[mt][ks][1] = f2tf32(sm[(r0 + 8) * SKS + col    ] * scale);
            qh[mt][ks][2] = f2tf32(sm[(r0    ) * SKS + col + 4] * scale);
            qh[mt][ks][3] = f2tf32(sm[(r0 + 8) * SKS + col + 4] * scale);
        }
    }
    __syncthreads();

    unsigned* Pw = Psu + wid * 32 * SPS;

    float out[2][8][4];
    #pragma unroll
    for (int mt = 0; mt < 2; mt++)
        #pragma unroll
        for (int nt = 0; nt < 8; nt++)
            #pragma unroll
            for (int r = 0; r < 4; r++) out[mt][nt][r] = 0.f;

    float mA[2][2], lA[2][2];
    #pragma unroll
    for (int mt = 0; mt < 2; mt++) {
        mA[mt][0] = -INFINITY; mA[mt][1] = -INFINITY;
        lA[mt][0] = 0.f;       lA[mt][1] = 0.f;
    }

    const int T = NTOT / ABC;

    for (int it = 0; it < T; it++) {
        if (it) __syncthreads();     // prior iteration's PV reads done

        // ---- load K,V tile: fused LDG->cvt->STS (no staging arrays) --------
        const float* kt = Kg + (size_t)it * ABC * DH;
        const float* vt = Vg + (size_t)it * ABC * DH;
        #pragma unroll
        for (int i = 0; i < 8; i++) {
            int f = tid + i * 128;
            int row = f >> 4, c4 = (f & 15) * 4;
            float4 k4 = *(const float4*)(kt + row * DH + c4);
            unsigned* p = &Ksu[row * SKS + c4];
            p[0] = f2tf32(k4.x); p[1] = f2tf32(k4.y);
            p[2] = f2tf32(k4.z); p[3] = f2tf32(k4.w);
            float4 v4 = *(const float4*)(vt + row * DH + c4);
            unsigned* q = &Vsu[row * SVS + c4];
            q[0] = f2tf32(v4.x); q[1] = f2tf32(v4.y);
            q[2] = f2tf32(v4.z); q[3] = f2tf32(v4.w);
        }
        __syncthreads();

        // ---- S = Q K^T (K-frags shared across both m-frags) ----------------
        float s[2][8][4];
        #pragma unroll
        for (int mt = 0; mt < 2; mt++)
            #pragma unroll
            for (int nt = 0; nt < 8; nt++)
                #pragma unroll
                for (int r = 0; r < 4; r++) s[mt][nt][r] = 0.f;

        #pragma unroll
        for (int ks = 0; ks < 8; ks++) {
            #pragma unroll
            for (int nt = 0; nt < 8; nt++) {
                unsigned bf[2];
                bf[0] = Ksu[(nt * 8 + g) * SKS + ks * 8 + t4    ];
                bf[1] = Ksu[(nt * 8 + g) * SKS + ks * 8 + t4 + 4];
                mma_tf32(s[0][nt], qh[0][ks], bf);
                mma_tf32(s[1][nt], qh[1][ks], bf);
            }
        }

        // ---- online softmax (per m-frag) ----------------------------------
        #pragma unroll
        for (int mt = 0; mt < 2; mt++) {
            float mx0 = mA[mt][0], mx1 = mA[mt][1];
            #pragma unroll
            for (int nt = 0; nt < 8; nt++) {
                mx0 = fmaxf(mx0, fmaxf(s[mt][nt][0], s[mt][nt][1]));
                mx1 = fmaxf(mx1, fmaxf(s[mt][nt][2], s[mt][nt][3]));
            }
            mx0 = fmaxf(mx0, __shfl_xor_sync(0xffffffffu, mx0, 1));
            mx0 = fmaxf(mx0, __shfl_xor_sync(0xffffffffu, mx0, 2));
            mx1 = fmaxf(mx1, __shfl_xor_sync(0xffffffffu, mx1, 1));
            mx1 = fmaxf(mx1, __shfl_xor_sync(0xffffffffu, mx1, 2));

            float c0 = __expf(mA[mt][0] - mx0);
            float c1 = __expf(mA[mt][1] - mx1);
            mA[mt][0] = mx0; mA[mt][1] = mx1;

            float rs0 = 0.f, rs1 = 0.f;
            #pragma unroll
            for (int nt = 0; nt < 8; nt++) {
                float p0 = __expf(s[mt][nt][0] - mx0);
                float p1 = __expf(s[mt][nt][1] - mx0);
                float p2 = __expf(s[mt][nt][2] - mx1);
                float p3 = __expf(s[mt][nt][3] - mx1);
                rs0 += p0 + p1;
                rs1 += p2 + p3;
                int r0 = mt * 16 + g;
                Pw[(r0    ) * SPS + nt * 8 + 2 * t4    ] = f2tf32(p0);
                Pw[(r0    ) * SPS + nt * 8 + 2 * t4 + 1] = f2tf32(p1);
                Pw[(r0 + 8) * SPS + nt * 8 + 2 * t4    ] = f2tf32(p2);
                Pw[(r0 + 8) * SPS + nt * 8 + 2 * t4 + 1] = f2tf32(p3);
            }
            rs0 += __shfl_xor_sync(0xffffffffu, rs0, 1);
            rs0 += __shfl_xor_sync(0xffffffffu, rs0, 2);
            rs1 += __shfl_xor_sync(0xffffffffu, rs1, 1);
            rs1 += __shfl_xor_sync(0xffffffffu, rs1, 2);
            lA[mt][0] = lA[mt][0] * c0 + rs0;
            lA[mt][1] = lA[mt][1] * c1 + rs1;

            #pragma unroll
            for (int nt = 0; nt < 8; nt++) {
                out[mt][nt][0] *= c0; out[mt][nt][1] *= c0;
                out[mt][nt][2] *= c1; out[mt][nt][3] *= c1;
            }
        }
        __syncwarp();

        // ---- out += P V (V-frags shared across both m-frags) ---------------
        #pragma unroll
        for (int ks = 0; ks < 8; ks++) {
            unsigned af[2][4];
            #pragma unroll
            for (int mt = 0; mt < 2; mt++) {
                int r0 = mt * 16 + g;
                af[mt][0] = Pw[(r0    ) * SPS + ks * 8 + t4    ];
                af[mt][1] = Pw[(r0 + 8) * SPS + ks * 8 + t4    ];
                af[mt][2] = Pw[(r0    ) * SPS + ks * 8 + t4 + 4];
                af[mt][3] = Pw[(r0 + 8) * SPS + ks * 8 + t4 + 4];
            }
            #pragma unroll
            for (int nt = 0; nt < 8; nt++) {
                unsigned bf2[2];
                bf2[0] = Vsu[(ks * 8 + t4    ) * SVS + nt * 8 + g];
                bf2[1] = Vsu[(ks * 8 + t4 + 4) * SVS + nt * 8 + g];
                mma_tf32(out[0][nt], af[0], bf2);
                mma_tf32(out[1][nt], af[1], bf2);
            }
        }
    }

    // ---- epilogue: normalize, write to g_o in [B, N1, h*64+d] --------------
    #pragma unroll
    for (int mt = 0; mt < 2; mt++) {
        float inv0 = 1.f / lA[mt][0];
        float inv1 = 1.f / lA[mt][1];
        int r0 = qb * ABR + wm + mt * 16 + g;
        int r1 = r0 + 8;
        float* o0 = g_o + ((size_t)b * SEQ1 + r0) * INNER + h * DH;
        float* o1 = g_o + ((size_t)b * SEQ1 + r1) * INNER + h * DH;
        #pragma unroll
        for (int nt = 0; nt < 8; nt++) {
            int col = nt * 8 + 2 * t4;
            *(float2*)&o0[col] = make_float2(out[mt][nt][0] * inv0, out[mt][nt][1] * inv0);
            *(float2*)&o1[col] = make_float2(out[mt][nt][2] * inv1, out[mt][nt][3] * inv1);
        }
    }
}

// ---------------- launch ----------------------------------------------------
extern "C" void kernel_launch(void* const* d_in, const int* in_sizes, int n_in,
                              void* d_out, int out_size)
{
    (void)in_sizes; (void)n_in; (void)out_size;
    const float* x1  = (const float*)d_in[0];
    const float* x2  = (const float*)d_in[1];
    const float* Wq1 = (const float*)d_in[2];
    const float* Wk1 = (const float*)d_in[3];
    const float* Wv1 = (const float*)d_in[4];
    const float* Wk2 = (const float*)d_in[5];
    const float* Wv2 = (const float*)d_in[6];
    const float* Wo  = (const float*)d_in[7];
    const float* bo  = (const float*)d_in[8];
    float* out = (float*)d_out;

    float *q, *k, *v, *o;
    cudaGetSymbolAddress((void**)&q, g_q);
    cudaGetSymbolAddress((void**)&k, g_k);
    cudaGetSymbolAddress((void**)&v, g_v);
    cudaGetSymbolAddress((void**)&o, g_o);

    static int attr_done = 0;
    if (!attr_done) {
        cudaFuncSetAttribute(proj_kernel, cudaFuncAttributeMaxDynamicSharedMemorySize, GEMM_SMEM);
        cudaFuncSetAttribute(out_kernel,  cudaFuncAttributeMaxDynamicSharedMemorySize, GEMM_SMEM);
        cudaFuncSetAttribute(attn_tc_kernel, cudaFuncAttributeMaxDynamicSharedMemorySize, ATTN_SMEM);
        attr_done = 1;
    }

    const int M = BATCH * SEQ1;   // 8192

    proj_kernel<<<dim3(INNER / GBN, M / GBM, 5), dim3(256), GEMM_SMEM>>>(
        x1, x2, Wq1, Wk1, Wv1, Wk2, Wv2, q, k, v);

    attn_tc_kernel<<<dim3(SEQ1 / ABR, HEADS, BATCH), dim3(128), ATTN_SMEM>>>();

    out_kernel<<<dim3(DMODEL / GBN, M / GBM), dim3(256), GEMM_SMEM>>>(o, Wo, bo, out);
}